// round 2
// baseline (speedup 1.0000x reference)
#include <cuda_runtime.h>
#include <math.h>
#include <stdint.h>

#define T_STEPS 16
#define BATCH   8192
#define IN_F    64
#define HID     256
#define OUT_F   64
#define NCLS    8

// ---- d_out layout (floats), tuple flattened in reference-return order ----
#define SZ_OUTSEQ (T_STEPS*BATCH*NCLS)     // 1,048,576
#define SZ_HC     (BATCH*HID)              // 2,097,152
#define SZ_SEQ    (T_STEPS*BATCH*HID)      // 33,554,432
#define OFF_OUTSEQ 0
#define OFF_HC1   (OFF_OUTSEQ + SZ_OUTSEQ)
#define OFF_HC2   (OFF_HC1 + SZ_HC)
#define OFF_HC3   (OFF_HC2 + SZ_HC)
#define OFF_HC4   (OFF_HC3 + SZ_HC)
#define OFF_I2H   (OFF_HC4 + SZ_HC)
#define OFF_H2H   (OFF_I2H + SZ_SEQ)

// Hidden-state double buffer (no cudaMalloc allowed -> device global scratch)
__device__ float g_hbuf[2][BATCH * HID];

// ============================================================================
// Kernel 1: i2h_seq = x @ W_i2h^T + b_i2h
// A=[131072,64] (lda=64), B=W_i2h [256,64] (ldb=64), C=[131072,256]
// Tile 128x128, BK=16, 256 threads, 8x8 per thread.
// ============================================================================
__global__ __launch_bounds__(256, 2)
void i2h_kernel(const float* __restrict__ X, const float* __restrict__ W,
                const float* __restrict__ bias, float* __restrict__ C)
{
    __shared__ float As[16][128];
    __shared__ float Bs[16][128];
    const int tid = threadIdx.x;
    const int tx = tid & 15, ty = tid >> 4;
    const int m0 = blockIdx.y * 128, n0 = blockIdx.x * 128;

    float acc[8][8];
    #pragma unroll
    for (int i = 0; i < 8; i++)
        #pragma unroll
        for (int j = 0; j < 8; j++) acc[i][j] = 0.f;

    for (int kt = 0; kt < IN_F; kt += 16) {
        #pragma unroll
        for (int it = 0; it < 2; it++) {
            int idx = tid + it * 256;          // 0..511
            int r  = idx >> 2;                 // 0..127
            int kv = (idx & 3) << 2;           // 0,4,8,12
            float4 a = *(const float4*)(X + (size_t)(m0 + r) * IN_F + kt + kv);
            As[kv + 0][r] = a.x; As[kv + 1][r] = a.y;
            As[kv + 2][r] = a.z; As[kv + 3][r] = a.w;
            float4 b = *(const float4*)(W + (size_t)(n0 + r) * IN_F + kt + kv);
            Bs[kv + 0][r] = b.x; Bs[kv + 1][r] = b.y;
            Bs[kv + 2][r] = b.z; Bs[kv + 3][r] = b.w;
        }
        __syncthreads();
        #pragma unroll
        for (int kk = 0; kk < 16; kk++) {
            float a[8], b[8];
            *(float4*)(a)     = *(const float4*)&As[kk][ty * 8];
            *(float4*)(a + 4) = *(const float4*)&As[kk][ty * 8 + 4];
            *(float4*)(b)     = *(const float4*)&Bs[kk][tx * 8];
            *(float4*)(b + 4) = *(const float4*)&Bs[kk][tx * 8 + 4];
            #pragma unroll
            for (int i = 0; i < 8; i++)
                #pragma unroll
                for (int j = 0; j < 8; j++) acc[i][j] += a[i] * b[j];
        }
        __syncthreads();
    }

    float bb[8];
    *(float4*)(bb)     = *(const float4*)&bias[n0 + tx * 8];
    *(float4*)(bb + 4) = *(const float4*)&bias[n0 + tx * 8 + 4];
    #pragma unroll
    for (int i = 0; i < 8; i++) {
        size_t base = (size_t)(m0 + ty * 8 + i) * HID + n0 + tx * 8;
        float4 v0 = make_float4(acc[i][0] + bb[0], acc[i][1] + bb[1],
                                acc[i][2] + bb[2], acc[i][3] + bb[3]);
        float4 v1 = make_float4(acc[i][4] + bb[4], acc[i][5] + bb[5],
                                acc[i][6] + bb[6], acc[i][7] + bb[7]);
        *(float4*)(C + base)     = v0;
        *(float4*)(C + base + 4) = v1;
    }
}

// ============================================================================
// Kernel 2 (per step): h2h = H @ W_h2h^T + b;  H_new = tanh(i2h_t + h2h)
// A=[8192,256] (prev hidden), B=W_h2h [256,256], both K-major (lda=ldb=256).
// Writes h2h_seq[t] (d_out) and H_new (double-buffered scratch; also hc1_final
// on the last step).
// ============================================================================
__global__ __launch_bounds__(256, 2)
void step_kernel(const float* __restrict__ hc1_in, int rd, int wr,
                 const float* __restrict__ W, const float* __restrict__ bias,
                 const float* __restrict__ i2h_t, float* __restrict__ h2h_out,
                 float* __restrict__ hc1f)
{
    __shared__ float As[16][128];
    __shared__ float Bs[16][128];
    const int tid = threadIdx.x;
    const int tx = tid & 15, ty = tid >> 4;
    const int m0 = blockIdx.y * 128, n0 = blockIdx.x * 128;

    const float* __restrict__ A = hc1_in ? hc1_in : g_hbuf[rd];
    float* __restrict__ Hn = g_hbuf[wr];

    float acc[8][8];
    #pragma unroll
    for (int i = 0; i < 8; i++)
        #pragma unroll
        for (int j = 0; j < 8; j++) acc[i][j] = 0.f;

    for (int kt = 0; kt < HID; kt += 16) {
        #pragma unroll
        for (int it = 0; it < 2; it++) {
            int idx = tid + it * 256;
            int r  = idx >> 2;
            int kv = (idx & 3) << 2;
            float4 a = *(const float4*)(A + (size_t)(m0 + r) * HID + kt + kv);
            As[kv + 0][r] = a.x; As[kv + 1][r] = a.y;
            As[kv + 2][r] = a.z; As[kv + 3][r] = a.w;
            float4 b = *(const float4*)(W + (size_t)(n0 + r) * HID + kt + kv);
            Bs[kv + 0][r] = b.x; Bs[kv + 1][r] = b.y;
            Bs[kv + 2][r] = b.z; Bs[kv + 3][r] = b.w;
        }
        __syncthreads();
        #pragma unroll
        for (int kk = 0; kk < 16; kk++) {
            float a[8], b[8];
            *(float4*)(a)     = *(const float4*)&As[kk][ty * 8];
            *(float4*)(a + 4) = *(const float4*)&As[kk][ty * 8 + 4];
            *(float4*)(b)     = *(const float4*)&Bs[kk][tx * 8];
            *(float4*)(b + 4) = *(const float4*)&Bs[kk][tx * 8 + 4];
            #pragma unroll
            for (int i = 0; i < 8; i++)
                #pragma unroll
                for (int j = 0; j < 8; j++) acc[i][j] += a[i] * b[j];
        }
        __syncthreads();
    }

    float bb[8];
    *(float4*)(bb)     = *(const float4*)&bias[n0 + tx * 8];
    *(float4*)(bb + 4) = *(const float4*)&bias[n0 + tx * 8 + 4];
    #pragma unroll
    for (int i = 0; i < 8; i++) {
        size_t base = (size_t)(m0 + ty * 8 + i) * HID + n0 + tx * 8;
        float v[8];
        #pragma unroll
        for (int j = 0; j < 8; j++) v[j] = acc[i][j] + bb[j];
        // store pre-tanh h2h (includes bias, matches reference)
        *(float4*)(h2h_out + base)     = make_float4(v[0], v[1], v[2], v[3]);
        *(float4*)(h2h_out + base + 4) = make_float4(v[4], v[5], v[6], v[7]);
        float4 ia = *(const float4*)(i2h_t + base);
        float4 ib = *(const float4*)(i2h_t + base + 4);
        float h[8];
        h[0] = tanhf(ia.x + v[0]); h[1] = tanhf(ia.y + v[1]);
        h[2] = tanhf(ia.z + v[2]); h[3] = tanhf(ia.w + v[3]);
        h[4] = tanhf(ib.x + v[4]); h[5] = tanhf(ib.y + v[5]);
        h[6] = tanhf(ib.z + v[6]); h[7] = tanhf(ib.w + v[7]);
        float4 h0 = make_float4(h[0], h[1], h[2], h[3]);
        float4 h1 = make_float4(h[4], h[5], h[6], h[7]);
        *(float4*)(Hn + base)     = h0;
        *(float4*)(Hn + base + 4) = h1;
        if (hc1f) {
            *(float4*)(hc1f + base)     = h0;
            *(float4*)(hc1f + base + 4) = h1;
        }
    }
}

// ============================================================================
// Kernel 3: head.  hs = tanh(i2h+h2h) (recomputed on the fly),
// O = tanh(hs @ W_h2o^T + b_h2o) [128x64 tile in smem],
// outseq = O @ W_fcc^T + b_fcc.
// BM=128, BN=64 (full), BK=16; 256 threads, 8x4 per thread.
// ============================================================================
__global__ __launch_bounds__(256, 2)
void head_kernel(const float* __restrict__ i2h, const float* __restrict__ h2h,
                 const float* __restrict__ Wo, const float* __restrict__ bo,
                 const float* __restrict__ Wf, const float* __restrict__ bf,
                 float* __restrict__ outseq)
{
    __shared__ float sbuf[8704];      // mainloop: As[16][128]|Bs[16][64]; epilogue: Osm[128][68]
    __shared__ float wf[NCLS * OUT_F];
    __shared__ float bfs[NCLS];
    float (*As)[128] = (float(*)[128])sbuf;
    float (*Bs)[64]  = (float(*)[64])(sbuf + 16 * 128);

    const int tid = threadIdx.x;
    wf[tid]       = Wf[tid];
    wf[tid + 256] = Wf[tid + 256];
    if (tid < NCLS) bfs[tid] = bf[tid];

    const int tx = tid & 15, ty = tid >> 4;
    const int m0 = blockIdx.y * 128;

    float acc[8][4];
    #pragma unroll
    for (int i = 0; i < 8; i++)
        #pragma unroll
        for (int j = 0; j < 4; j++) acc[i][j] = 0.f;

    for (int kt = 0; kt < HID; kt += 16) {
        #pragma unroll
        for (int it = 0; it < 2; it++) {
            int idx = tid + it * 256;
            int r  = idx >> 2;
            int kv = (idx & 3) << 2;
            size_t base = (size_t)(m0 + r) * HID + kt + kv;
            float4 va = *(const float4*)(i2h + base);
            float4 vb = *(const float4*)(h2h + base);
            As[kv + 0][r] = tanhf(va.x + vb.x);
            As[kv + 1][r] = tanhf(va.y + vb.y);
            As[kv + 2][r] = tanhf(va.z + vb.z);
            As[kv + 3][r] = tanhf(va.w + vb.w);
        }
        {
            int r  = tid >> 2;                // 0..63
            int kv = (tid & 3) << 2;
            float4 w = *(const float4*)(Wo + (size_t)r * HID + kt + kv);
            Bs[kv + 0][r] = w.x; Bs[kv + 1][r] = w.y;
            Bs[kv + 2][r] = w.z; Bs[kv + 3][r] = w.w;
        }
        __syncthreads();
        #pragma unroll
        for (int kk = 0; kk < 16; kk++) {
            float a[8], b[4];
            *(float4*)(a)     = *(const float4*)&As[kk][ty * 8];
            *(float4*)(a + 4) = *(const float4*)&As[kk][ty * 8 + 4];
            *(float4*)(b)     = *(const float4*)&Bs[kk][tx * 4];
            #pragma unroll
            for (int i = 0; i < 8; i++)
                #pragma unroll
                for (int j = 0; j < 4; j++) acc[i][j] += a[i] * b[j];
        }
        __syncthreads();
    }

    // Epilogue: O tile -> smem (overlays As/Bs; all reads drained by last sync)
    float bb[4];
    *(float4*)bb = *(const float4*)&bo[tx * 4];
    float* Osm = sbuf;                 // pitch 68 floats
    #pragma unroll
    for (int i = 0; i < 8; i++) {
        float4 v;
        v.x = tanhf(acc[i][0] + bb[0]);
        v.y = tanhf(acc[i][1] + bb[1]);
        v.z = tanhf(acc[i][2] + bb[2]);
        v.w = tanhf(acc[i][3] + bb[3]);
        *(float4*)(Osm + (ty * 8 + i) * 68 + tx * 4) = v;
    }
    __syncthreads();

    // Final fcc: 128 rows x 8 classes = 1024 outputs, 4 per thread
    #pragma unroll
    for (int i = 0; i < 4; i++) {
        int idx = tid + i * 256;
        int row = idx >> 3;
        int c   = idx & 7;
        const float* orow = Osm + row * 68;
        const float* wr   = wf + c * OUT_F;
        float s = bfs[c];
        #pragma unroll
        for (int o = 0; o < OUT_F; o++) s += orow[o] * wr[o];
        outseq[(size_t)(m0 + row) * NCLS + c] = s;
    }
}

// ============================================================================
extern "C" void kernel_launch(void* const* d_in, const int* in_sizes, int n_in,
                              void* d_out, int out_size)
{
    const float* x      = (const float*)d_in[0];
    // d_in[1] = cue (unused by reference's meaningful outputs)
    const float* hc1    = (const float*)d_in[2];
    const float* hc2    = (const float*)d_in[3];
    const float* hc3    = (const float*)d_in[4];
    const float* hc4    = (const float*)d_in[5];
    const float* W_i2h  = (const float*)d_in[6];
    const float* b_i2h  = (const float*)d_in[7];
    const float* W_h2h  = (const float*)d_in[8];
    const float* b_h2h  = (const float*)d_in[9];
    const float* W_h2o  = (const float*)d_in[10];
    const float* b_h2o  = (const float*)d_in[11];
    const float* W_fcc  = (const float*)d_in[12];
    const float* b_fcc  = (const float*)d_in[13];

    float* out = (float*)d_out;
    float* i2h_seq = out + OFF_I2H;
    float* h2h_seq = out + OFF_H2H;

    // Pass-throughs
    cudaMemcpyAsync(out + OFF_HC2, hc2, (size_t)SZ_HC * sizeof(float),
                    cudaMemcpyDeviceToDevice);
    cudaMemcpyAsync(out + OFF_HC3, hc3, (size_t)SZ_HC * sizeof(float),
                    cudaMemcpyDeviceToDevice);
    cudaMemcpyAsync(out + OFF_HC4, hc4, (size_t)SZ_HC * sizeof(float),
                    cudaMemcpyDeviceToDevice);

    // 1) i2h over all timesteps
    dim3 g1(HID / 128, (T_STEPS * BATCH) / 128);
    i2h_kernel<<<g1, 256>>>(x, W_i2h, b_i2h, i2h_seq);

    // 2) sequential recurrence
    dim3 g2(HID / 128, BATCH / 128);
    for (int t = 0; t < T_STEPS; t++) {
        step_kernel<<<g2, 256>>>(
            (t == 0) ? hc1 : nullptr,
            (t + 1) & 1, t & 1,
            W_h2h, b_h2h,
            i2h_seq + (size_t)t * BATCH * HID,
            h2h_seq + (size_t)t * BATCH * HID,
            (t == T_STEPS - 1) ? (out + OFF_HC1) : nullptr);
    }

    // 3) output head (recomputes hs = tanh(i2h+h2h) on the fly)
    dim3 g3(1, (T_STEPS * BATCH) / 128);
    head_kernel<<<g3, 256>>>(i2h_seq, h2h_seq, W_h2o, b_h2o, W_fcc, b_fcc,
                             out + OFF_OUTSEQ);
}

// round 6
// speedup vs baseline: 1.0386x; 1.0386x over previous
#include <cuda_runtime.h>
#include <cuda_bf16.h>
#include <math.h>
#include <stdint.h>

#define T_STEPS 16
#define BATCH   8192
#define IN_F    64
#define HID     256
#define OUT_F   64
#define NCLS    8

// ---- d_out layout (floats), tuple flattened in reference-return order ----
#define SZ_OUTSEQ (T_STEPS*BATCH*NCLS)
#define SZ_HC     (BATCH*HID)
#define SZ_SEQ    (T_STEPS*BATCH*HID)
#define OFF_OUTSEQ 0
#define OFF_HC1   (OFF_OUTSEQ + SZ_OUTSEQ)
#define OFF_HC2   (OFF_HC1 + SZ_HC)
#define OFF_HC3   (OFF_HC2 + SZ_HC)
#define OFF_HC4   (OFF_HC3 + SZ_HC)
#define OFF_I2H   (OFF_HC4 + SZ_HC)
#define OFF_H2H   (OFF_I2H + SZ_SEQ)

// ---------------- device scratch (no cudaMalloc allowed) ----------------
__device__ float g_h[BATCH * HID];                    // recurrent state (fp32)
__device__ __nv_bfloat16 g_Whi[HID * HID];            // W_h2h bf16 hi, [n][k]
__device__ __nv_bfloat16 g_Wlo[HID * HID];            // W_h2h bf16 lo, [n][k]

__device__ __forceinline__ uint32_t pack2(__nv_bfloat16 a, __nv_bfloat16 b) {
    __nv_bfloat162 t; t.x = a; t.y = b;
    return *(uint32_t*)&t;
}

// mma.sync m16n8k16 bf16 (baseline ISA, works on compute_103)
#define MMA16816(c, a, b) \
    asm volatile("mma.sync.aligned.m16n8k16.row.col.f32.bf16.bf16.f32 " \
        "{%0,%1,%2,%3}, {%4,%5,%6,%7}, {%8,%9}, {%0,%1,%2,%3};" \
        : "+f"((c)[0]), "+f"((c)[1]), "+f"((c)[2]), "+f"((c)[3]) \
        : "r"((a)[0]), "r"((a)[1]), "r"((a)[2]), "r"((a)[3]), \
          "r"((b)[0]), "r"((b)[1]))

// ============================================================================
// prep_w: split W_h2h (fp32 [n][k]) into bf16 hi/lo globals.
// ============================================================================
__global__ void prep_w(const float* __restrict__ W)
{
    int idx = blockIdx.x * 256 + threadIdx.x;     // 0..65535
    float v = W[idx];
    __nv_bfloat16 hi = __float2bfloat16(v);
    __nv_bfloat16 lo = __float2bfloat16(v - __bfloat162float(hi));
    g_Whi[idx] = hi;
    g_Wlo[idx] = lo;
}

// ============================================================================
// step_mma: one recurrence step via mma.sync bf16 hi/lo split.
//   h2h = A @ W^T + b (fp32-equivalent);  h_new = tanh(i2h + h2h)
// CTA tile: 128m x 128n.  Warps: 4m x 2n -> warp tile 32m x 64n.
// smem: Whi/Wlo [128][264] (full K=256, padded), Ahi/Alo [128][136] (K chunk 128).
// ============================================================================
#define WPITCH 264
#define APITCH 136
#define STEP_SMEM ((2 * 128 * WPITCH + 2 * 128 * APITCH) * 2)   // 204800 B

__global__ __launch_bounds__(256, 1)
void step_mma(const float* __restrict__ hc1_in,
              const float* __restrict__ bias,
              const float* __restrict__ i2h_t,
              float* __restrict__ h2h_out,
              float* __restrict__ hc1f)
{
    extern __shared__ __nv_bfloat16 sm[];
    __nv_bfloat16* sWhi = sm;                         // [128][WPITCH]
    __nv_bfloat16* sWlo = sWhi + 128 * WPITCH;
    __nv_bfloat16* sAhi = sWlo + 128 * WPITCH;        // [128][APITCH]
    __nv_bfloat16* sAlo = sAhi + 128 * APITCH;

    const int tid = threadIdx.x;
    const int n0 = blockIdx.x * 128;
    const int m0 = blockIdx.y * 128;

    const float* __restrict__ A = hc1_in ? hc1_in : g_h;

    // ---- load W half (128 n-rows, full K) into smem ----
    #pragma unroll
    for (int i = tid; i < 4096; i += 256) {
        int n = i >> 5;
        int k8 = (i & 31) * 8;
        *(uint4*)(sWhi + n * WPITCH + k8) =
            *(const uint4*)(g_Whi + (size_t)(n0 + n) * HID + k8);
        *(uint4*)(sWlo + n * WPITCH + k8) =
            *(const uint4*)(g_Wlo + (size_t)(n0 + n) * HID + k8);
    }

    const int w = tid >> 5, lane = tid & 31;
    const int mwb = (w >> 1) * 32;      // warp m base within CTA
    const int nwb = (w & 1) * 64;       // warp n base within CTA
    const int tq = lane >> 2, tr = lane & 3;

    float acc[2][8][4];
    #pragma unroll
    for (int mb = 0; mb < 2; mb++)
        #pragma unroll
        for (int nb = 0; nb < 8; nb++)
            #pragma unroll
            for (int q = 0; q < 4; q++) acc[mb][nb][q] = 0.f;

    for (int c = 0; c < 2; c++) {
        // ---- load + split A chunk [128 m][128 k] fp32 -> bf16 hi/lo ----
        if (c) __syncthreads();     // drain MMAs of previous chunk
        #pragma unroll
        for (int i = tid; i < 4096; i += 256) {
            int m = i >> 5;
            int kq = (i & 31) * 4;
            float4 v = *(const float4*)(A + (size_t)(m0 + m) * HID + c * 128 + kq);
            __nv_bfloat16 hx = __float2bfloat16(v.x);
            __nv_bfloat16 hy = __float2bfloat16(v.y);
            __nv_bfloat16 hz = __float2bfloat16(v.z);
            __nv_bfloat16 hw = __float2bfloat16(v.w);
            uint2 hv, lv;
            hv.x = pack2(hx, hy); hv.y = pack2(hz, hw);
            lv.x = pack2(__float2bfloat16(v.x - __bfloat162float(hx)),
                         __float2bfloat16(v.y - __bfloat162float(hy)));
            lv.y = pack2(__float2bfloat16(v.z - __bfloat162float(hz)),
                         __float2bfloat16(v.w - __bfloat162float(hw)));
            *(uint2*)(sAhi + m * APITCH + kq) = hv;
            *(uint2*)(sAlo + m * APITCH + kq) = lv;
        }
        __syncthreads();

        const int kg0 = c * 128;
        #pragma unroll 4
        for (int kk = 0; kk < 128; kk += 16) {
            // A fragments (hi & lo) for 2 m-blocks
            uint32_t ah[2][4], al[2][4];
            #pragma unroll
            for (int mb = 0; mb < 2; mb++) {
                const __nv_bfloat16* ba =
                    sAhi + (mwb + mb * 16 + tq) * APITCH + kk + tr * 2;
                ah[mb][0] = *(const uint32_t*)(ba);
                ah[mb][1] = *(const uint32_t*)(ba + 8 * APITCH);
                ah[mb][2] = *(const uint32_t*)(ba + 8);
                ah[mb][3] = *(const uint32_t*)(ba + 8 * APITCH + 8);
                const __nv_bfloat16* bl =
                    sAlo + (mwb + mb * 16 + tq) * APITCH + kk + tr * 2;
                al[mb][0] = *(const uint32_t*)(bl);
                al[mb][1] = *(const uint32_t*)(bl + 8 * APITCH);
                al[mb][2] = *(const uint32_t*)(bl + 8);
                al[mb][3] = *(const uint32_t*)(bl + 8 * APITCH + 8);
            }
            // B fragments (hi & lo) for 8 n-blocks
            uint32_t bh[8][2], bl2[8][2];
            #pragma unroll
            for (int nb = 0; nb < 8; nb++) {
                const __nv_bfloat16* bb =
                    sWhi + (nwb + nb * 8 + tq) * WPITCH + kg0 + kk + tr * 2;
                bh[nb][0] = *(const uint32_t*)(bb);
                bh[nb][1] = *(const uint32_t*)(bb + 8);
                const __nv_bfloat16* bc =
                    sWlo + (nwb + nb * 8 + tq) * WPITCH + kg0 + kk + tr * 2;
                bl2[nb][0] = *(const uint32_t*)(bc);
                bl2[nb][1] = *(const uint32_t*)(bc + 8);
            }
            #pragma unroll
            for (int mb = 0; mb < 2; mb++)
                #pragma unroll
                for (int nb = 0; nb < 8; nb++) {
                    MMA16816(acc[mb][nb], ah[mb], bh[nb]);
                    MMA16816(acc[mb][nb], ah[mb], bl2[nb]);
                    MMA16816(acc[mb][nb], al[mb], bh[nb]);
                }
        }
    }

    // ---- epilogue: +bias, write h2h; tanh(i2h + h2h) -> g_h (+hc1f) ----
    #pragma unroll
    for (int mb = 0; mb < 2; mb++) {
        #pragma unroll
        for (int nb = 0; nb < 8; nb++) {
            int gr = m0 + mwb + mb * 16 + tq;
            int gc = n0 + nwb + nb * 8 + tr * 2;
            float2 bv = *(const float2*)(bias + gc);
            #pragma unroll
            for (int half = 0; half < 2; half++) {
                int r = gr + half * 8;
                float p0 = acc[mb][nb][half * 2 + 0] + bv.x;
                float p1 = acc[mb][nb][half * 2 + 1] + bv.y;
                size_t off = (size_t)r * HID + gc;
                *(float2*)(h2h_out + off) = make_float2(p0, p1);
                float2 iv = *(const float2*)(i2h_t + off);
                float2 hn = make_float2(tanhf(iv.x + p0), tanhf(iv.y + p1));
                *(float2*)(g_h + off) = hn;
                if (hc1f) *(float2*)(hc1f + off) = hn;
            }
        }
    }
}

// ============================================================================
// Kernel 1: i2h_seq = x @ W_i2h^T + b_i2h   (fp32 FFMA, unchanged)
// ============================================================================
__global__ __launch_bounds__(256, 2)
void i2h_kernel(const float* __restrict__ X, const float* __restrict__ W,
                const float* __restrict__ bias, float* __restrict__ C)
{
    __shared__ float As[16][128];
    __shared__ float Bs[16][128];
    const int tid = threadIdx.x;
    const int tx = tid & 15, ty = tid >> 4;
    const int m0 = blockIdx.y * 128, n0 = blockIdx.x * 128;

    float acc[8][8];
    #pragma unroll
    for (int i = 0; i < 8; i++)
        #pragma unroll
        for (int j = 0; j < 8; j++) acc[i][j] = 0.f;

    for (int kt = 0; kt < IN_F; kt += 16) {
        #pragma unroll
        for (int it = 0; it < 2; it++) {
            int idx = tid + it * 256;
            int r  = idx >> 2;
            int kv = (idx & 3) << 2;
            float4 a = *(const float4*)(X + (size_t)(m0 + r) * IN_F + kt + kv);
            As[kv + 0][r] = a.x; As[kv + 1][r] = a.y;
            As[kv + 2][r] = a.z; As[kv + 3][r] = a.w;
            float4 b = *(const float4*)(W + (size_t)(n0 + r) * IN_F + kt + kv);
            Bs[kv + 0][r] = b.x; Bs[kv + 1][r] = b.y;
            Bs[kv + 2][r] = b.z; Bs[kv + 3][r] = b.w;
        }
        __syncthreads();
        #pragma unroll
        for (int kk = 0; kk < 16; kk++) {
            float a[8], b[8];
            *(float4*)(a)     = *(const float4*)&As[kk][ty * 8];
            *(float4*)(a + 4) = *(const float4*)&As[kk][ty * 8 + 4];
            *(float4*)(b)     = *(const float4*)&Bs[kk][tx * 8];
            *(float4*)(b + 4) = *(const float4*)&Bs[kk][tx * 8 + 4];
            #pragma unroll
            for (int i = 0; i < 8; i++)
                #pragma unroll
                for (int j = 0; j < 8; j++) acc[i][j] += a[i] * b[j];
        }
        __syncthreads();
    }

    float bb[8];
    *(float4*)(bb)     = *(const float4*)&bias[n0 + tx * 8];
    *(float4*)(bb + 4) = *(const float4*)&bias[n0 + tx * 8 + 4];
    #pragma unroll
    for (int i = 0; i < 8; i++) {
        size_t base = (size_t)(m0 + ty * 8 + i) * HID + n0 + tx * 8;
        *(float4*)(C + base) = make_float4(acc[i][0] + bb[0], acc[i][1] + bb[1],
                                           acc[i][2] + bb[2], acc[i][3] + bb[3]);
        *(float4*)(C + base + 4) = make_float4(acc[i][4] + bb[4], acc[i][5] + bb[5],
                                               acc[i][6] + bb[6], acc[i][7] + bb[7]);
    }
}

// ============================================================================
// Kernel 3: head (fp32 FFMA, unchanged)
// ============================================================================
__global__ __launch_bounds__(256, 2)
void head_kernel(const float* __restrict__ i2h, const float* __restrict__ h2h,
                 const float* __restrict__ Wo, const float* __restrict__ bo,
                 const float* __restrict__ Wf, const float* __restrict__ bf,
                 float* __restrict__ outseq)
{
    __shared__ float sbuf[8704];
    __shared__ float wf[NCLS * OUT_F];
    __shared__ float bfs[NCLS];
    float (*As)[128] = (float(*)[128])sbuf;
    float (*Bs)[64]  = (float(*)[64])(sbuf + 16 * 128);

    const int tid = threadIdx.x;
    wf[tid]       = Wf[tid];
    wf[tid + 256] = Wf[tid + 256];
    if (tid < NCLS) bfs[tid] = bf[tid];

    const int tx = tid & 15, ty = tid >> 4;
    const int m0 = blockIdx.y * 128;

    float acc[8][4];
    #pragma unroll
    for (int i = 0; i < 8; i++)
        #pragma unroll
        for (int j = 0; j < 4; j++) acc[i][j] = 0.f;

    for (int kt = 0; kt < HID; kt += 16) {
        #pragma unroll
        for (int it = 0; it < 2; it++) {
            int idx = tid + it * 256;
            int r  = idx >> 2;
            int kv = (idx & 3) << 2;
            size_t base = (size_t)(m0 + r) * HID + kt + kv;
            float4 va = *(const float4*)(i2h + base);
            float4 vb = *(const float4*)(h2h + base);
            As[kv + 0][r] = tanhf(va.x + vb.x);
            As[kv + 1][r] = tanhf(va.y + vb.y);
            As[kv + 2][r] = tanhf(va.z + vb.z);
            As[kv + 3][r] = tanhf(va.w + vb.w);
        }
        {
            int r  = tid >> 2;
            int kv = (tid & 3) << 2;
            float4 wv = *(const float4*)(Wo + (size_t)r * HID + kt + kv);
            Bs[kv + 0][r] = wv.x; Bs[kv + 1][r] = wv.y;
            Bs[kv + 2][r] = wv.z; Bs[kv + 3][r] = wv.w;
        }
        __syncthreads();
        #pragma unroll
        for (int kk = 0; kk < 16; kk++) {
            float a[8], b[4];
            *(float4*)(a)     = *(const float4*)&As[kk][ty * 8];
            *(float4*)(a + 4) = *(const float4*)&As[kk][ty * 8 + 4];
            *(float4*)(b)     = *(const float4*)&Bs[kk][tx * 4];
            #pragma unroll
            for (int i = 0; i < 8; i++)
                #pragma unroll
                for (int j = 0; j < 4; j++) acc[i][j] += a[i] * b[j];
        }
        __syncthreads();
    }

    float bb[4];
    *(float4*)bb = *(const float4*)&bo[tx * 4];
    float* Osm = sbuf;
    #pragma unroll
    for (int i = 0; i < 8; i++) {
        float4 v;
        v.x = tanhf(acc[i][0] + bb[0]);
        v.y = tanhf(acc[i][1] + bb[1]);
        v.z = tanhf(acc[i][2] + bb[2]);
        v.w = tanhf(acc[i][3] + bb[3]);
        *(float4*)(Osm + (ty * 8 + i) * 68 + tx * 4) = v;
    }
    __syncthreads();

    #pragma unroll
    for (int i = 0; i < 4; i++) {
        int idx = tid + i * 256;
        int row = idx >> 3;
        int c   = idx & 7;
        const float* orow = Osm + row * 68;
        const float* wr   = wf + c * OUT_F;
        float s = bfs[c];
        #pragma unroll
        for (int o = 0; o < OUT_F; o++) s += orow[o] * wr[o];
        outseq[(size_t)(m0 + row) * NCLS + c] = s;
    }
}

// ============================================================================
extern "C" void kernel_launch(void* const* d_in, const int* in_sizes, int n_in,
                              void* d_out, int out_size)
{
    const float* x      = (const float*)d_in[0];
    const float* hc1    = (const float*)d_in[2];
    const float* hc2    = (const float*)d_in[3];
    const float* hc3    = (const float*)d_in[4];
    const float* hc4    = (const float*)d_in[5];
    const float* W_i2h  = (const float*)d_in[6];
    const float* b_i2h  = (const float*)d_in[7];
    const float* W_h2h  = (const float*)d_in[8];
    const float* b_h2h  = (const float*)d_in[9];
    const float* W_h2o  = (const float*)d_in[10];
    const float* b_h2o  = (const float*)d_in[11];
    const float* W_fcc  = (const float*)d_in[12];
    const float* b_fcc  = (const float*)d_in[13];

    float* out = (float*)d_out;
    float* i2h_seq = out + OFF_I2H;
    float* h2h_seq = out + OFF_H2H;

    cudaFuncSetAttribute(step_mma, cudaFuncAttributeMaxDynamicSharedMemorySize,
                         STEP_SMEM);

    cudaMemcpyAsync(out + OFF_HC2, hc2, (size_t)SZ_HC * sizeof(float),
                    cudaMemcpyDeviceToDevice);
    cudaMemcpyAsync(out + OFF_HC3, hc3, (size_t)SZ_HC * sizeof(float),
                    cudaMemcpyDeviceToDevice);
    cudaMemcpyAsync(out + OFF_HC4, hc4, (size_t)SZ_HC * sizeof(float),
                    cudaMemcpyDeviceToDevice);

    // 0) split W_h2h into bf16 hi/lo
    prep_w<<<256, 256>>>(W_h2h);

    // 1) i2h over all timesteps
    dim3 g1(HID / 128, (T_STEPS * BATCH) / 128);
    i2h_kernel<<<g1, 256>>>(x, W_i2h, b_i2h, i2h_seq);

    // 2) sequential recurrence (mma.sync bf16 split)
    dim3 g2(2, BATCH / 128);
    for (int t = 0; t < T_STEPS; t++) {
        step_mma<<<g2, 256, STEP_SMEM>>>(
            (t == 0) ? hc1 : nullptr,
            b_h2h,
            i2h_seq + (size_t)t * BATCH * HID,
            h2h_seq + (size_t)t * BATCH * HID,
            (t == T_STEPS - 1) ? (out + OFF_HC1) : nullptr);
    }

    // 3) output head
    dim3 g3(1, (T_STEPS * BATCH) / 128);
    head_kernel<<<g3, 256>>>(i2h_seq, h2h_seq, W_h2o, b_h2o, W_fcc, b_fcc,
                             out + OFF_OUTSEQ);
}

// round 9
// speedup vs baseline: 1.6063x; 1.5466x over previous
#include <cuda_runtime.h>
#include <cuda_bf16.h>
#include <math.h>
#include <stdint.h>

#define T_STEPS 16
#define BATCH   8192
#define IN_F    64
#define HID     256
#define OUT_F   64
#define NCLS    8

// ---- d_out layout (floats), tuple flattened in reference-return order ----
#define SZ_OUTSEQ (T_STEPS*BATCH*NCLS)
#define SZ_HC     (BATCH*HID)
#define SZ_SEQ    (T_STEPS*BATCH*HID)
#define OFF_OUTSEQ 0
#define OFF_HC1   (OFF_OUTSEQ + SZ_OUTSEQ)
#define OFF_HC2   (OFF_HC1 + SZ_HC)
#define OFF_HC3   (OFF_HC2 + SZ_HC)
#define OFF_HC4   (OFF_HC3 + SZ_HC)
#define OFF_I2H   (OFF_HC4 + SZ_HC)
#define OFF_H2H   (OFF_I2H + SZ_SEQ)

// ---------------- device scratch (no cudaMalloc allowed) ----------------
__device__ float g_h[BATCH * HID];                    // recurrent state (fp32)
__device__ __nv_bfloat16 g_Whi[HID * HID];            // W_h2h bf16 hi, [n][k]
__device__ __nv_bfloat16 g_Wlo[HID * HID];            // W_h2h bf16 lo, [n][k]

__device__ __forceinline__ uint32_t pack2(__nv_bfloat16 a, __nv_bfloat16 b) {
    __nv_bfloat162 t; t.x = a; t.y = b;
    return *(uint32_t*)&t;
}
__device__ __forceinline__ uint32_t smem_u32(const void* p) {
    uint32_t a;
    asm("{ .reg .u64 t; cvta.to.shared.u64 t, %1; cvt.u32.u64 %0, t; }"
        : "=r"(a) : "l"(p));
    return a;
}
__device__ __forceinline__ float tanh_ap(float x) {
    float y;
    asm("tanh.approx.f32 %0, %1;" : "=f"(y) : "f"(x));
    return y;
}

// mma.sync m16n8k16 bf16 (baseline ISA)
#define MMA16816(c, a, b) \
    asm volatile("mma.sync.aligned.m16n8k16.row.col.f32.bf16.bf16.f32 " \
        "{%0,%1,%2,%3}, {%4,%5,%6,%7}, {%8,%9}, {%0,%1,%2,%3};" \
        : "+f"((c)[0]), "+f"((c)[1]), "+f"((c)[2]), "+f"((c)[3]) \
        : "r"((a)[0]), "r"((a)[1]), "r"((a)[2]), "r"((a)[3]), \
          "r"((b)[0]), "r"((b)[1]))

#define LDSM4(r, addr) \
    asm volatile("ldmatrix.sync.aligned.m8n8.x4.shared.b16 {%0,%1,%2,%3}, [%4];" \
        : "=r"((r)[0]), "=r"((r)[1]), "=r"((r)[2]), "=r"((r)[3]) : "r"(addr))

// ============================================================================
// prep_w: split W_h2h (fp32 [n][k]) into bf16 hi/lo globals.
// ============================================================================
__global__ void prep_w(const float* __restrict__ W)
{
    int idx = blockIdx.x * 256 + threadIdx.x;
    float v = W[idx];
    __nv_bfloat16 hi = __float2bfloat16(v);
    __nv_bfloat16 lo = __float2bfloat16(v - __bfloat162float(hi));
    g_Whi[idx] = hi;
    g_Wlo[idx] = lo;
}

// ============================================================================
// step_mma v2: CTA 128m x 128n, 8 warps (4m x 2n), warp tile 32m x 64n.
// K chunked by 64 with double-buffered A (hi/lo) + register prefetch.
// ldmatrix fragment feed; MMA in 3 independent passes (hh, hl, lh).
// smem (bf16 elems): Whi[128*264] | Wlo[128*264] | A[2 buf][hi|lo][128*72]
// ============================================================================
#define WPITCH 264
#define APITCH 72
#define W_HALF_ELEMS (128 * WPITCH)               // 33792
#define A_HL_ELEMS   (128 * APITCH)               // 9216
#define A_BUF_ELEMS  (2 * A_HL_ELEMS)             // 18432
#define A_BASE_ELEMS (2 * W_HALF_ELEMS)           // 67584
#define STEP_SMEM ((A_BASE_ELEMS + 2 * A_BUF_ELEMS) * 2)   // 208896 B

__global__ __launch_bounds__(256, 1)
void step_mma(const float* __restrict__ hc1_in,
              const float* __restrict__ bias,
              const float* __restrict__ i2h_t,
              float* __restrict__ h2h_out,
              float* __restrict__ hc1f)
{
    extern __shared__ __nv_bfloat16 sm[];
    __nv_bfloat16* sWhi = sm;
    __nv_bfloat16* sWlo = sm + W_HALF_ELEMS;
    __nv_bfloat16* sA   = sm + A_BASE_ELEMS;      // [buf][hl][128*72]

    const int tid = threadIdx.x;
    const int n0 = blockIdx.x * 128;
    const int m0 = blockIdx.y * 128;

    const float* __restrict__ A = hc1_in ? hc1_in : g_h;

    // ---- load W half (128 n-rows, full K=256) into smem ----
    #pragma unroll
    for (int i = tid; i < 4096; i += 256) {
        int n = i >> 5;
        int k8 = (i & 31) * 8;
        *(uint4*)(sWhi + n * WPITCH + k8) =
            *(const uint4*)(g_Whi + (size_t)(n0 + n) * HID + k8);
        *(uint4*)(sWlo + n * WPITCH + k8) =
            *(const uint4*)(g_Wlo + (size_t)(n0 + n) * HID + k8);
    }

    const int w = tid >> 5, lane = tid & 31;
    const int mwb = (w >> 1) * 32;      // warp m base
    const int nwb = (w & 1) * 64;       // warp n base
    const int tq = lane >> 2, tr = lane & 3;
    const int quad = lane >> 3, rl = lane & 7;

    // ldmatrix per-lane byte offsets
    uint32_t a_off[2], b_off[4];
    #pragma unroll
    for (int mb = 0; mb < 2; mb++)
        a_off[mb] = (uint32_t)(((mwb + mb * 16 + rl + (quad & 1) * 8) * APITCH
                                + (quad >> 1) * 8) * 2);
    #pragma unroll
    for (int nbp = 0; nbp < 4; nbp++)
        b_off[nbp] = (uint32_t)(((nwb + (nbp * 2 + (quad >> 1)) * 8 + rl) * WPITCH
                                 + (quad & 1) * 8) * 2);

    const uint32_t smb  = smem_u32(sm);
    const uint32_t wHiB = smb;
    const uint32_t wLoB = smb + W_HALF_ELEMS * 2;
    const uint32_t aB   = smb + A_BASE_ELEMS * 2;

    float acc[2][8][4];
    #pragma unroll
    for (int mb = 0; mb < 2; mb++)
        #pragma unroll
        for (int nb = 0; nb < 8; nb++)
            #pragma unroll
            for (int q = 0; q < 4; q++) acc[mb][nb][q] = 0.f;

    // ---- prefetch chunk 0 (k=0..63) into regs ----
    float4 pf[8];
    #pragma unroll
    for (int it = 0; it < 8; it++) {
        int idx = tid + it * 256;
        int m = idx >> 4, kq = (idx & 15) * 4;
        pf[it] = *(const float4*)(A + (size_t)(m0 + m) * HID + kq);
    }
    // store split chunk 0 -> buf 0
    #pragma unroll
    for (int it = 0; it < 8; it++) {
        int idx = tid + it * 256;
        int m = idx >> 4, kq = (idx & 15) * 4;
        float4 v = pf[it];
        __nv_bfloat16 hx = __float2bfloat16(v.x);
        __nv_bfloat16 hy = __float2bfloat16(v.y);
        __nv_bfloat16 hz = __float2bfloat16(v.z);
        __nv_bfloat16 hw = __float2bfloat16(v.w);
        uint2 hv, lv;
        hv.x = pack2(hx, hy); hv.y = pack2(hz, hw);
        lv.x = pack2(__float2bfloat16(v.x - __bfloat162float(hx)),
                     __float2bfloat16(v.y - __bfloat162float(hy)));
        lv.y = pack2(__float2bfloat16(v.z - __bfloat162float(hz)),
                     __float2bfloat16(v.w - __bfloat162float(hw)));
        *(uint2*)(sA + 0 * A_BUF_ELEMS + m * APITCH + kq) = hv;
        *(uint2*)(sA + 0 * A_BUF_ELEMS + A_HL_ELEMS + m * APITCH + kq) = lv;
    }
    __syncthreads();

    for (int c = 0; c < 4; c++) {
        const int cur = c & 1, nxt = cur ^ 1;

        // prefetch chunk c+1 (regs only; no smem hazard)
        if (c < 3) {
            #pragma unroll
            for (int it = 0; it < 8; it++) {
                int idx = tid + it * 256;
                int m = idx >> 4, kq = (idx & 15) * 4;
                pf[it] = *(const float4*)(A + (size_t)(m0 + m) * HID
                                          + (c + 1) * 64 + kq);
            }
        }

        const uint32_t aHi = aB + cur * (A_BUF_ELEMS * 2);
        const uint32_t aLo = aHi + A_HL_ELEMS * 2;
        #pragma unroll
        for (int kk = 0; kk < 64; kk += 16) {
            uint32_t ah[2][4], al[2][4], bh[4][4], bl[4][4];
            #pragma unroll
            for (int mb = 0; mb < 2; mb++) {
                LDSM4(ah[mb], aHi + a_off[mb] + kk * 2);
                LDSM4(al[mb], aLo + a_off[mb] + kk * 2);
            }
            const uint32_t kb = (c * 64 + kk) * 2;
            #pragma unroll
            for (int nbp = 0; nbp < 4; nbp++) {
                LDSM4(bh[nbp], wHiB + b_off[nbp] + kb);
                LDSM4(bl[nbp], wLoB + b_off[nbp] + kb);
            }
            // pass 1: Ahi * Whi   (16 independent MMAs)
            #pragma unroll
            for (int nb = 0; nb < 8; nb++)
                #pragma unroll
                for (int mb = 0; mb < 2; mb++)
                    MMA16816(acc[mb][nb], ah[mb], &bh[nb >> 1][(nb & 1) * 2]);
            // pass 2: Ahi * Wlo
            #pragma unroll
            for (int nb = 0; nb < 8; nb++)
                #pragma unroll
                for (int mb = 0; mb < 2; mb++)
                    MMA16816(acc[mb][nb], ah[mb], &bl[nb >> 1][(nb & 1) * 2]);
            // pass 3: Alo * Whi
            #pragma unroll
            for (int nb = 0; nb < 8; nb++)
                #pragma unroll
                for (int mb = 0; mb < 2; mb++)
                    MMA16816(acc[mb][nb], al[mb], &bh[nb >> 1][(nb & 1) * 2]);
        }

        // store split chunk c+1 -> nxt buf, then sync
        if (c < 3) {
            #pragma unroll
            for (int it = 0; it < 8; it++) {
                int idx = tid + it * 256;
                int m = idx >> 4, kq = (idx & 15) * 4;
                float4 v = pf[it];
                __nv_bfloat16 hx = __float2bfloat16(v.x);
                __nv_bfloat16 hy = __float2bfloat16(v.y);
                __nv_bfloat16 hz = __float2bfloat16(v.z);
                __nv_bfloat16 hw = __float2bfloat16(v.w);
                uint2 hv, lv;
                hv.x = pack2(hx, hy); hv.y = pack2(hz, hw);
                lv.x = pack2(__float2bfloat16(v.x - __bfloat162float(hx)),
                             __float2bfloat16(v.y - __bfloat162float(hy)));
                lv.y = pack2(__float2bfloat16(v.z - __bfloat162float(hz)),
                             __float2bfloat16(v.w - __bfloat162float(hw)));
                *(uint2*)(sA + nxt * A_BUF_ELEMS + m * APITCH + kq) = hv;
                *(uint2*)(sA + nxt * A_BUF_ELEMS + A_HL_ELEMS + m * APITCH + kq) = lv;
            }
            __syncthreads();
        }
    }

    // ---- epilogue: +bias, write h2h; tanh(i2h + h2h) -> g_h (+hc1f) ----
    #pragma unroll
    for (int mb = 0; mb < 2; mb++) {
        #pragma unroll
        for (int nb = 0; nb < 8; nb++) {
            int gr = m0 + mwb + mb * 16 + tq;
            int gc = n0 + nwb + nb * 8 + tr * 2;
            float2 bv = *(const float2*)(bias + gc);
            #pragma unroll
            for (int half = 0; half < 2; half++) {
                int r = gr + half * 8;
                float p0 = acc[mb][nb][half * 2 + 0] + bv.x;
                float p1 = acc[mb][nb][half * 2 + 1] + bv.y;
                size_t off = (size_t)r * HID + gc;
                *(float2*)(h2h_out + off) = make_float2(p0, p1);
                float2 iv = *(const float2*)(i2h_t + off);
                float2 hn = make_float2(tanh_ap(iv.x + p0), tanh_ap(iv.y + p1));
                *(float2*)(g_h + off) = hn;
                if (hc1f) *(float2*)(hc1f + off) = hn;
            }
        }
    }
}

// ============================================================================
// Kernel 1: i2h_seq = x @ W_i2h^T + b_i2h   (fp32 FFMA, unchanged)
// ============================================================================
__global__ __launch_bounds__(256, 2)
void i2h_kernel(const float* __restrict__ X, const float* __restrict__ W,
                const float* __restrict__ bias, float* __restrict__ C)
{
    __shared__ float As[16][128];
    __shared__ float Bs[16][128];
    const int tid = threadIdx.x;
    const int tx = tid & 15, ty = tid >> 4;
    const int m0 = blockIdx.y * 128, n0 = blockIdx.x * 128;

    float acc[8][8];
    #pragma unroll
    for (int i = 0; i < 8; i++)
        #pragma unroll
        for (int j = 0; j < 8; j++) acc[i][j] = 0.f;

    for (int kt = 0; kt < IN_F; kt += 16) {
        #pragma unroll
        for (int it = 0; it < 2; it++) {
            int idx = tid + it * 256;
            int r  = idx >> 2;
            int kv = (idx & 3) << 2;
            float4 a = *(const float4*)(X + (size_t)(m0 + r) * IN_F + kt + kv);
            As[kv + 0][r] = a.x; As[kv + 1][r] = a.y;
            As[kv + 2][r] = a.z; As[kv + 3][r] = a.w;
            float4 b = *(const float4*)(W + (size_t)(n0 + r) * IN_F + kt + kv);
            Bs[kv + 0][r] = b.x; Bs[kv + 1][r] = b.y;
            Bs[kv + 2][r] = b.z; Bs[kv + 3][r] = b.w;
        }
        __syncthreads();
        #pragma unroll
        for (int kk = 0; kk < 16; kk++) {
            float a[8], b[8];
            *(float4*)(a)     = *(const float4*)&As[kk][ty * 8];
            *(float4*)(a + 4) = *(const float4*)&As[kk][ty * 8 + 4];
            *(float4*)(b)     = *(const float4*)&Bs[kk][tx * 8];
            *(float4*)(b + 4) = *(const float4*)&Bs[kk][tx * 8 + 4];
            #pragma unroll
            for (int i = 0; i < 8; i++)
                #pragma unroll
                for (int j = 0; j < 8; j++) acc[i][j] += a[i] * b[j];
        }
        __syncthreads();
    }

    float bb[8];
    *(float4*)(bb)     = *(const float4*)&bias[n0 + tx * 8];
    *(float4*)(bb + 4) = *(const float4*)&bias[n0 + tx * 8 + 4];
    #pragma unroll
    for (int i = 0; i < 8; i++) {
        size_t base = (size_t)(m0 + ty * 8 + i) * HID + n0 + tx * 8;
        *(float4*)(C + base) = make_float4(acc[i][0] + bb[0], acc[i][1] + bb[1],
                                           acc[i][2] + bb[2], acc[i][3] + bb[3]);
        *(float4*)(C + base + 4) = make_float4(acc[i][4] + bb[4], acc[i][5] + bb[5],
                                               acc[i][6] + bb[6], acc[i][7] + bb[7]);
    }
}

// ============================================================================
// Kernel 3: head (fp32 FFMA; tanh.approx)
// ============================================================================
__global__ __launch_bounds__(256, 2)
void head_kernel(const float* __restrict__ i2h, const float* __restrict__ h2h,
                 const float* __restrict__ Wo, const float* __restrict__ bo,
                 const float* __restrict__ Wf, const float* __restrict__ bf,
                 float* __restrict__ outseq)
{
    __shared__ float sbuf[8704];
    __shared__ float wf[NCLS * OUT_F];
    __shared__ float bfs[NCLS];
    float (*As)[128] = (float(*)[128])sbuf;
    float (*Bs)[64]  = (float(*)[64])(sbuf + 16 * 128);

    const int tid = threadIdx.x;
    wf[tid]       = Wf[tid];
    wf[tid + 256] = Wf[tid + 256];
    if (tid < NCLS) bfs[tid] = bf[tid];

    const int tx = tid & 15, ty = tid >> 4;
    const int m0 = blockIdx.y * 128;

    float acc[8][4];
    #pragma unroll
    for (int i = 0; i < 8; i++)
        #pragma unroll
        for (int j = 0; j < 4; j++) acc[i][j] = 0.f;

    for (int kt = 0; kt < HID; kt += 16) {
        #pragma unroll
        for (int it = 0; it < 2; it++) {
            int idx = tid + it * 256;
            int r  = idx >> 2;
            int kv = (idx & 3) << 2;
            size_t base = (size_t)(m0 + r) * HID + kt + kv;
            float4 va = *(const float4*)(i2h + base);
            float4 vb = *(const float4*)(h2h + base);
            As[kv + 0][r] = tanh_ap(va.x + vb.x);
            As[kv + 1][r] = tanh_ap(va.y + vb.y);
            As[kv + 2][r] = tanh_ap(va.z + vb.z);
            As[kv + 3][r] = tanh_ap(va.w + vb.w);
        }
        {
            int r  = tid >> 2;
            int kv = (tid & 3) << 2;
            float4 wv = *(const float4*)(Wo + (size_t)r * HID + kt + kv);
            Bs[kv + 0][r] = wv.x; Bs[kv + 1][r] = wv.y;
            Bs[kv + 2][r] = wv.z; Bs[kv + 3][r] = wv.w;
        }
        __syncthreads();
        #pragma unroll
        for (int kk = 0; kk < 16; kk++) {
            float a[8], b[4];
            *(float4*)(a)     = *(const float4*)&As[kk][ty * 8];
            *(float4*)(a + 4) = *(const float4*)&As[kk][ty * 8 + 4];
            *(float4*)(b)     = *(const float4*)&Bs[kk][tx * 4];
            #pragma unroll
            for (int i = 0; i < 8; i++)
                #pragma unroll
                for (int j = 0; j < 4; j++) acc[i][j] += a[i] * b[j];
        }
        __syncthreads();
    }

    float bb[4];
    *(float4*)bb = *(const float4*)&bo[tx * 4];
    float* Osm = sbuf;
    #pragma unroll
    for (int i = 0; i < 8; i++) {
        float4 v;
        v.x = tanh_ap(acc[i][0] + bb[0]);
        v.y = tanh_ap(acc[i][1] + bb[1]);
        v.z = tanh_ap(acc[i][2] + bb[2]);
        v.w = tanh_ap(acc[i][3] + bb[3]);
        *(float4*)(Osm + (ty * 8 + i) * 68 + tx * 4) = v;
    }
    __syncthreads();

    #pragma unroll
    for (int i = 0; i < 4; i++) {
        int idx = tid + i * 256;
        int row = idx >> 3;
        int c   = idx & 7;
        const float* orow = Osm + row * 68;
        const float* wr   = wf + c * OUT_F;
        float s = bfs[c];
        #pragma unroll
        for (int o = 0; o < OUT_F; o++) s += orow[o] * wr[o];
        outseq[(size_t)(m0 + row) * NCLS + c] = s;
    }
}

// ============================================================================
extern "C" void kernel_launch(void* const* d_in, const int* in_sizes, int n_in,
                              void* d_out, int out_size)
{
    const float* x      = (const float*)d_in[0];
    const float* hc1    = (const float*)d_in[2];
    const float* hc2    = (const float*)d_in[3];
    const float* hc3    = (const float*)d_in[4];
    const float* hc4    = (const float*)d_in[5];
    const float* W_i2h  = (const float*)d_in[6];
    const float* b_i2h  = (const float*)d_in[7];
    const float* W_h2h  = (const float*)d_in[8];
    const float* b_h2h  = (const float*)d_in[9];
    const float* W_h2o  = (const float*)d_in[10];
    const float* b_h2o  = (const float*)d_in[11];
    const float* W_fcc  = (const float*)d_in[12];
    const float* b_fcc  = (const float*)d_in[13];

    float* out = (float*)d_out;
    float* i2h_seq = out + OFF_I2H;
    float* h2h_seq = out + OFF_H2H;

    cudaFuncSetAttribute(step_mma, cudaFuncAttributeMaxDynamicSharedMemorySize,
                         STEP_SMEM);

    cudaMemcpyAsync(out + OFF_HC2, hc2, (size_t)SZ_HC * sizeof(float),
                    cudaMemcpyDeviceToDevice);
    cudaMemcpyAsync(out + OFF_HC3, hc3, (size_t)SZ_HC * sizeof(float),
                    cudaMemcpyDeviceToDevice);
    cudaMemcpyAsync(out + OFF_HC4, hc4, (size_t)SZ_HC * sizeof(float),
                    cudaMemcpyDeviceToDevice);

    // 0) split W_h2h into bf16 hi/lo
    prep_w<<<256, 256>>>(W_h2h);

    // 1) i2h over all timesteps
    dim3 g1(HID / 128, (T_STEPS * BATCH) / 128);
    i2h_kernel<<<g1, 256>>>(x, W_i2h, b_i2h, i2h_seq);

    // 2) sequential recurrence (mma.sync bf16 split, pipelined)
    dim3 g2(2, BATCH / 128);
    for (int t = 0; t < T_STEPS; t++) {
        step_mma<<<g2, 256, STEP_SMEM>>>(
            (t == 0) ? hc1 : nullptr,
            b_h2h,
            i2h_seq + (size_t)t * BATCH * HID,
            h2h_seq + (size_t)t * BATCH * HID,
            (t == T_STEPS - 1) ? (out + OFF_HC1) : nullptr);
    }

    // 3) output head
    dim3 g3(1, (T_STEPS * BATCH) / 128);
    head_kernel<<<g3, 256>>>(i2h_seq, h2h_seq, W_h2o, b_h2o, W_fcc, b_fcc,
                             out + OFF_OUTSEQ);
}

// round 11
// speedup vs baseline: 2.0203x; 1.2578x over previous
#include <cuda_runtime.h>
#include <cuda_bf16.h>
#include <math.h>
#include <stdint.h>

#define T_STEPS 16
#define BATCH   8192
#define IN_F    64
#define HID     256
#define OUT_F   64
#define NCLS    8

// ---- d_out layout (floats), tuple flattened in reference-return order ----
#define SZ_OUTSEQ (T_STEPS*BATCH*NCLS)
#define SZ_HC     (BATCH*HID)
#define SZ_SEQ    (T_STEPS*BATCH*HID)
#define OFF_OUTSEQ 0
#define OFF_HC1   (OFF_OUTSEQ + SZ_OUTSEQ)
#define OFF_HC2   (OFF_HC1 + SZ_HC)
#define OFF_HC3   (OFF_HC2 + SZ_HC)
#define OFF_HC4   (OFF_HC3 + SZ_HC)
#define OFF_I2H   (OFF_HC4 + SZ_HC)
#define OFF_H2H   (OFF_I2H + SZ_SEQ)

// ---------------- device scratch (no cudaMalloc allowed) ----------------
__device__ float g_h[BATCH * HID];                 // recurrent state (fp32)
__device__ __nv_bfloat16 g_Whi[HID * HID];         // W_h2h hi, [n][k]
__device__ __nv_bfloat16 g_Wlo[HID * HID];         // W_h2h lo
__device__ __nv_bfloat16 g_Wihi[HID * IN_F];       // W_i2h hi, [n][k]
__device__ __nv_bfloat16 g_Wilo[HID * IN_F];       // W_i2h lo
__device__ __nv_bfloat16 g_Wohi[OUT_F * HID];      // W_h2o hi, [n][k]
__device__ __nv_bfloat16 g_Wolo[OUT_F * HID];      // W_h2o lo

__device__ __forceinline__ uint32_t pack2(__nv_bfloat16 a, __nv_bfloat16 b) {
    __nv_bfloat162 t; t.x = a; t.y = b;
    return *(uint32_t*)&t;
}
__device__ __forceinline__ uint32_t smem_u32(const void* p) {
    uint32_t a;
    asm("{ .reg .u64 t; cvta.to.shared.u64 t, %1; cvt.u32.u64 %0, t; }"
        : "=r"(a) : "l"(p));
    return a;
}
__device__ __forceinline__ float tanh_ap(float x) {
    float y;
    asm("tanh.approx.f32 %0, %1;" : "=f"(y) : "f"(x));
    return y;
}
__device__ __forceinline__ void split_store(__nv_bfloat16* hiDst,
                                            __nv_bfloat16* loDst, float4 v) {
    __nv_bfloat16 hx = __float2bfloat16(v.x);
    __nv_bfloat16 hy = __float2bfloat16(v.y);
    __nv_bfloat16 hz = __float2bfloat16(v.z);
    __nv_bfloat16 hw = __float2bfloat16(v.w);
    uint2 hv, lv;
    hv.x = pack2(hx, hy); hv.y = pack2(hz, hw);
    lv.x = pack2(__float2bfloat16(v.x - __bfloat162float(hx)),
                 __float2bfloat16(v.y - __bfloat162float(hy)));
    lv.y = pack2(__float2bfloat16(v.z - __bfloat162float(hz)),
                 __float2bfloat16(v.w - __bfloat162float(hw)));
    *(uint2*)hiDst = hv;
    *(uint2*)loDst = lv;
}

// mma.sync m16n8k16 bf16 (baseline ISA)
#define MMA16816(c, a, b) \
    asm volatile("mma.sync.aligned.m16n8k16.row.col.f32.bf16.bf16.f32 " \
        "{%0,%1,%2,%3}, {%4,%5,%6,%7}, {%8,%9}, {%0,%1,%2,%3};" \
        : "+f"((c)[0]), "+f"((c)[1]), "+f"((c)[2]), "+f"((c)[3]) \
        : "r"((a)[0]), "r"((a)[1]), "r"((a)[2]), "r"((a)[3]), \
          "r"((b)[0]), "r"((b)[1]))

#define LDSM4(r, addr) \
    asm volatile("ldmatrix.sync.aligned.m8n8.x4.shared.b16 {%0,%1,%2,%3}, [%4];" \
        : "=r"((r)[0]), "=r"((r)[1]), "=r"((r)[2]), "=r"((r)[3]) : "r"(addr))

// ============================================================================
// prep kernels: split fp32 weights into bf16 hi/lo globals.
// ============================================================================
__global__ void prep_w(const float* __restrict__ W)
{
    int idx = blockIdx.x * 256 + threadIdx.x;
    float v = W[idx];
    __nv_bfloat16 hi = __float2bfloat16(v);
    g_Whi[idx] = hi;
    g_Wlo[idx] = __float2bfloat16(v - __bfloat162float(hi));
}
__global__ void prep_wi(const float* __restrict__ W)
{
    int idx = blockIdx.x * 256 + threadIdx.x;     // 16384
    float v = W[idx];
    __nv_bfloat16 hi = __float2bfloat16(v);
    g_Wihi[idx] = hi;
    g_Wilo[idx] = __float2bfloat16(v - __bfloat162float(hi));
}
__global__ void prep_wo(const float* __restrict__ W)
{
    int idx = blockIdx.x * 256 + threadIdx.x;     // 16384
    float v = W[idx];
    __nv_bfloat16 hi = __float2bfloat16(v);
    g_Wohi[idx] = hi;
    g_Wolo[idx] = __float2bfloat16(v - __bfloat162float(hi));
}

// ============================================================================
// step_mma (unchanged from R9): CTA 128m x 128n, 8 warps (4m x 2n).
// ============================================================================
#define WPITCH 264
#define APITCH 72
#define W_HALF_ELEMS (128 * WPITCH)
#define A_HL_ELEMS   (128 * APITCH)
#define A_BUF_ELEMS  (2 * A_HL_ELEMS)
#define A_BASE_ELEMS (2 * W_HALF_ELEMS)
#define STEP_SMEM ((A_BASE_ELEMS + 2 * A_BUF_ELEMS) * 2)

__global__ __launch_bounds__(256, 1)
void step_mma(const float* __restrict__ hc1_in,
              const float* __restrict__ bias,
              const float* __restrict__ i2h_t,
              float* __restrict__ h2h_out,
              float* __restrict__ hc1f)
{
    extern __shared__ __nv_bfloat16 sm[];
    __nv_bfloat16* sWhi = sm;
    __nv_bfloat16* sWlo = sm + W_HALF_ELEMS;
    __nv_bfloat16* sA   = sm + A_BASE_ELEMS;

    const int tid = threadIdx.x;
    const int n0 = blockIdx.x * 128;
    const int m0 = blockIdx.y * 128;

    const float* __restrict__ A = hc1_in ? hc1_in : g_h;

    #pragma unroll
    for (int i = tid; i < 4096; i += 256) {
        int n = i >> 5;
        int k8 = (i & 31) * 8;
        *(uint4*)(sWhi + n * WPITCH + k8) =
            *(const uint4*)(g_Whi + (size_t)(n0 + n) * HID + k8);
        *(uint4*)(sWlo + n * WPITCH + k8) =
            *(const uint4*)(g_Wlo + (size_t)(n0 + n) * HID + k8);
    }

    const int w = tid >> 5, lane = tid & 31;
    const int mwb = (w >> 1) * 32;
    const int nwb = (w & 1) * 64;
    const int tq = lane >> 2, tr = lane & 3;
    const int quad = lane >> 3, rl = lane & 7;

    uint32_t a_off[2], b_off[4];
    #pragma unroll
    for (int mb = 0; mb < 2; mb++)
        a_off[mb] = (uint32_t)(((mwb + mb * 16 + rl + (quad & 1) * 8) * APITCH
                                + (quad >> 1) * 8) * 2);
    #pragma unroll
    for (int nbp = 0; nbp < 4; nbp++)
        b_off[nbp] = (uint32_t)(((nwb + (nbp * 2 + (quad >> 1)) * 8 + rl) * WPITCH
                                 + (quad & 1) * 8) * 2);

    const uint32_t smb  = smem_u32(sm);
    const uint32_t wHiB = smb;
    const uint32_t wLoB = smb + W_HALF_ELEMS * 2;
    const uint32_t aB   = smb + A_BASE_ELEMS * 2;

    float acc[2][8][4];
    #pragma unroll
    for (int mb = 0; mb < 2; mb++)
        #pragma unroll
        for (int nb = 0; nb < 8; nb++)
            #pragma unroll
            for (int q = 0; q < 4; q++) acc[mb][nb][q] = 0.f;

    float4 pf[8];
    #pragma unroll
    for (int it = 0; it < 8; it++) {
        int idx = tid + it * 256;
        int m = idx >> 4, kq = (idx & 15) * 4;
        pf[it] = *(const float4*)(A + (size_t)(m0 + m) * HID + kq);
    }
    #pragma unroll
    for (int it = 0; it < 8; it++) {
        int idx = tid + it * 256;
        int m = idx >> 4, kq = (idx & 15) * 4;
        split_store(sA + m * APITCH + kq,
                    sA + A_HL_ELEMS + m * APITCH + kq, pf[it]);
    }
    __syncthreads();

    for (int c = 0; c < 4; c++) {
        const int cur = c & 1, nxt = cur ^ 1;

        if (c < 3) {
            #pragma unroll
            for (int it = 0; it < 8; it++) {
                int idx = tid + it * 256;
                int m = idx >> 4, kq = (idx & 15) * 4;
                pf[it] = *(const float4*)(A + (size_t)(m0 + m) * HID
                                          + (c + 1) * 64 + kq);
            }
        }

        const uint32_t aHi = aB + cur * (A_BUF_ELEMS * 2);
        const uint32_t aLo = aHi + A_HL_ELEMS * 2;
        #pragma unroll
        for (int kk = 0; kk < 64; kk += 16) {
            uint32_t ah[2][4], al[2][4], bh[4][4], bl[4][4];
            #pragma unroll
            for (int mb = 0; mb < 2; mb++) {
                LDSM4(ah[mb], aHi + a_off[mb] + kk * 2);
                LDSM4(al[mb], aLo + a_off[mb] + kk * 2);
            }
            const uint32_t kb = (c * 64 + kk) * 2;
            #pragma unroll
            for (int nbp = 0; nbp < 4; nbp++) {
                LDSM4(bh[nbp], wHiB + b_off[nbp] + kb);
                LDSM4(bl[nbp], wLoB + b_off[nbp] + kb);
            }
            #pragma unroll
            for (int nb = 0; nb < 8; nb++)
                #pragma unroll
                for (int mb = 0; mb < 2; mb++)
                    MMA16816(acc[mb][nb], ah[mb], &bh[nb >> 1][(nb & 1) * 2]);
            #pragma unroll
            for (int nb = 0; nb < 8; nb++)
                #pragma unroll
                for (int mb = 0; mb < 2; mb++)
                    MMA16816(acc[mb][nb], ah[mb], &bl[nb >> 1][(nb & 1) * 2]);
            #pragma unroll
            for (int nb = 0; nb < 8; nb++)
                #pragma unroll
                for (int mb = 0; mb < 2; mb++)
                    MMA16816(acc[mb][nb], al[mb], &bh[nb >> 1][(nb & 1) * 2]);
        }

        if (c < 3) {
            #pragma unroll
            for (int it = 0; it < 8; it++) {
                int idx = tid + it * 256;
                int m = idx >> 4, kq = (idx & 15) * 4;
                split_store(sA + nxt * A_BUF_ELEMS + m * APITCH + kq,
                            sA + nxt * A_BUF_ELEMS + A_HL_ELEMS + m * APITCH + kq,
                            pf[it]);
            }
            __syncthreads();
        }
    }

    #pragma unroll
    for (int mb = 0; mb < 2; mb++) {
        #pragma unroll
        for (int nb = 0; nb < 8; nb++) {
            int gr = m0 + mwb + mb * 16 + tq;
            int gc = n0 + nwb + nb * 8 + tr * 2;
            float2 bv = *(const float2*)(bias + gc);
            #pragma unroll
            for (int half = 0; half < 2; half++) {
                int r = gr + half * 8;
                float p0 = acc[mb][nb][half * 2 + 0] + bv.x;
                float p1 = acc[mb][nb][half * 2 + 1] + bv.y;
                size_t off = (size_t)r * HID + gc;
                *(float2*)(h2h_out + off) = make_float2(p0, p1);
                float2 iv = *(const float2*)(i2h_t + off);
                float2 hn = make_float2(tanh_ap(iv.x + p0), tanh_ap(iv.y + p1));
                *(float2*)(g_h + off) = hn;
                if (hc1f) *(float2*)(hc1f + off) = hn;
            }
        }
    }
}

// ============================================================================
// i2h_mma: C = X @ W_i2h^T + b.  M=131072, N=256, K=64 (4 k16 iters).
// CTA 128m x 128n, warps 4m x 2n; both operands hi/lo split, 3 passes.
// smem: sWhi/sWlo [128][72], sAhi/sAlo [128][72].
// ============================================================================
#define IAP 72
#define I2H_SMEM (4 * 128 * IAP * 2)

__global__ __launch_bounds__(256, 1)
void i2h_mma(const float* __restrict__ X,
             const float* __restrict__ bias,
             float* __restrict__ C)
{
    extern __shared__ __nv_bfloat16 ism[];
    __nv_bfloat16* sWhi = ism;
    __nv_bfloat16* sWlo = sWhi + 128 * IAP;
    __nv_bfloat16* sAhi = sWlo + 128 * IAP;
    __nv_bfloat16* sAlo = sAhi + 128 * IAP;

    const int tid = threadIdx.x;
    const int n0 = blockIdx.x * 128;
    const int m0 = blockIdx.y * 128;

    #pragma unroll
    for (int i = tid; i < 1024; i += 256) {
        int n = i >> 3, k8 = (i & 7) * 8;
        *(uint4*)(sWhi + n * IAP + k8) =
            *(const uint4*)(g_Wihi + (size_t)(n0 + n) * IN_F + k8);
        *(uint4*)(sWlo + n * IAP + k8) =
            *(const uint4*)(g_Wilo + (size_t)(n0 + n) * IN_F + k8);
    }
    #pragma unroll
    for (int it = 0; it < 8; it++) {
        int idx = tid + it * 256;
        int m = idx >> 4, kq = (idx & 15) * 4;
        float4 v = *(const float4*)(X + (size_t)(m0 + m) * IN_F + kq);
        split_store(sAhi + m * IAP + kq, sAlo + m * IAP + kq, v);
    }
    __syncthreads();

    const int w = tid >> 5, lane = tid & 31;
    const int mwb = (w >> 1) * 32;
    const int nwb = (w & 1) * 64;
    const int tq = lane >> 2, tr = lane & 3;
    const int quad = lane >> 3, rl = lane & 7;

    uint32_t a_off[2], b_off[4];
    #pragma unroll
    for (int mb = 0; mb < 2; mb++)
        a_off[mb] = (uint32_t)(((mwb + mb * 16 + rl + (quad & 1) * 8) * IAP
                                + (quad >> 1) * 8) * 2);
    #pragma unroll
    for (int nbp = 0; nbp < 4; nbp++)
        b_off[nbp] = (uint32_t)(((nwb + (nbp * 2 + (quad >> 1)) * 8 + rl) * IAP
                                 + (quad & 1) * 8) * 2);

    const uint32_t smb = smem_u32(ism);
    const uint32_t wHiB = smb;
    const uint32_t wLoB = smb + 128 * IAP * 2;
    const uint32_t aHiB = smb + 2 * 128 * IAP * 2;
    const uint32_t aLoB = smb + 3 * 128 * IAP * 2;

    float acc[2][8][4];
    #pragma unroll
    for (int mb = 0; mb < 2; mb++)
        #pragma unroll
        for (int nb = 0; nb < 8; nb++)
            #pragma unroll
            for (int q = 0; q < 4; q++) acc[mb][nb][q] = 0.f;

    #pragma unroll
    for (int kk = 0; kk < 64; kk += 16) {
        uint32_t ah[2][4], al[2][4], bh[4][4], bl[4][4];
        #pragma unroll
        for (int mb = 0; mb < 2; mb++) {
            LDSM4(ah[mb], aHiB + a_off[mb] + kk * 2);
            LDSM4(al[mb], aLoB + a_off[mb] + kk * 2);
        }
        #pragma unroll
        for (int nbp = 0; nbp < 4; nbp++) {
            LDSM4(bh[nbp], wHiB + b_off[nbp] + kk * 2);
            LDSM4(bl[nbp], wLoB + b_off[nbp] + kk * 2);
        }
        #pragma unroll
        for (int nb = 0; nb < 8; nb++)
            #pragma unroll
            for (int mb = 0; mb < 2; mb++)
                MMA16816(acc[mb][nb], ah[mb], &bh[nb >> 1][(nb & 1) * 2]);
        #pragma unroll
        for (int nb = 0; nb < 8; nb++)
            #pragma unroll
            for (int mb = 0; mb < 2; mb++)
                MMA16816(acc[mb][nb], ah[mb], &bl[nb >> 1][(nb & 1) * 2]);
        #pragma unroll
        for (int nb = 0; nb < 8; nb++)
            #pragma unroll
            for (int mb = 0; mb < 2; mb++)
                MMA16816(acc[mb][nb], al[mb], &bh[nb >> 1][(nb & 1) * 2]);
    }

    #pragma unroll
    for (int mb = 0; mb < 2; mb++) {
        #pragma unroll
        for (int nb = 0; nb < 8; nb++) {
            int gr = m0 + mwb + mb * 16 + tq;
            int gc = n0 + nwb + nb * 8 + tr * 2;
            float2 bv = *(const float2*)(bias + gc);
            #pragma unroll
            for (int half = 0; half < 2; half++) {
                size_t off = (size_t)(gr + half * 8) * HID + gc;
                *(float2*)(C + off) =
                    make_float2(acc[mb][nb][half * 2 + 0] + bv.x,
                                acc[mb][nb][half * 2 + 1] + bv.y);
            }
        }
    }
}

// ============================================================================
// head_mma: A = tanh(i2h+h2h) [128m x 256k] split on the fly (double-buffered
// k=64 chunks), B = W_h2o [64n x 256k] split; O = tanh(A@B^T + bo);
// outseq = O @ W_fcc^T + bf (smem epilogue).
// Warps 4m x 2n -> warp 32m x 32n.
// ============================================================================
#define HWP 264
#define HAP 72
#define HW_ELEMS (64 * HWP)
#define HA_HL   (128 * HAP)
#define HA_BUF  (2 * HA_HL)
#define HA_BASE (2 * HW_ELEMS)
#define HEAD_SMEM ((HA_BASE + 2 * HA_BUF) * 2)

__global__ __launch_bounds__(256, 1)
void head_mma(const float* __restrict__ i2h, const float* __restrict__ h2h,
              const float* __restrict__ bo,
              const float* __restrict__ Wf, const float* __restrict__ bf,
              float* __restrict__ outseq)
{
    extern __shared__ __nv_bfloat16 hsm[];
    __nv_bfloat16* sWhi = hsm;
    __nv_bfloat16* sWlo = hsm + HW_ELEMS;
    __nv_bfloat16* sA   = hsm + HA_BASE;
    __shared__ float wf[NCLS * OUT_F];
    __shared__ float bfs[NCLS];

    const int tid = threadIdx.x;
    const int m0 = blockIdx.x * 128;

    wf[tid]       = Wf[tid];
    wf[tid + 256] = Wf[tid + 256];
    if (tid < NCLS) bfs[tid] = bf[tid];

    #pragma unroll
    for (int i = tid; i < 2048; i += 256) {
        int n = i >> 5, k8 = (i & 31) * 8;
        *(uint4*)(sWhi + n * HWP + k8) =
            *(const uint4*)(g_Wohi + (size_t)n * HID + k8);
        *(uint4*)(sWlo + n * HWP + k8) =
            *(const uint4*)(g_Wolo + (size_t)n * HID + k8);
    }

    const int w = tid >> 5, lane = tid & 31;
    const int mwb = (w >> 1) * 32;
    const int nwb = (w & 1) * 32;
    const int tq = lane >> 2, tr = lane & 3;
    const int quad = lane >> 3, rl = lane & 7;

    uint32_t a_off[2], b_off[2];
    #pragma unroll
    for (int mb = 0; mb < 2; mb++)
        a_off[mb] = (uint32_t)(((mwb + mb * 16 + rl + (quad & 1) * 8) * HAP
                                + (quad >> 1) * 8) * 2);
    #pragma unroll
    for (int nbp = 0; nbp < 2; nbp++)
        b_off[nbp] = (uint32_t)(((nwb + (nbp * 2 + (quad >> 1)) * 8 + rl) * HWP
                                 + (quad & 1) * 8) * 2);

    const uint32_t smb = smem_u32(hsm);
    const uint32_t wHiB = smb;
    const uint32_t wLoB = smb + HW_ELEMS * 2;
    const uint32_t aB   = smb + HA_BASE * 2;

    float acc[2][4][4];
    #pragma unroll
    for (int mb = 0; mb < 2; mb++)
        #pragma unroll
        for (int nb = 0; nb < 4; nb++)
            #pragma unroll
            for (int q = 0; q < 4; q++) acc[mb][nb][q] = 0.f;

    float4 pfi[8], pfh[8];
    #pragma unroll
    for (int it = 0; it < 8; it++) {
        int idx = tid + it * 256;
        int m = idx >> 4, kq = (idx & 15) * 4;
        size_t off = (size_t)(m0 + m) * HID + kq;
        pfi[it] = *(const float4*)(i2h + off);
        pfh[it] = *(const float4*)(h2h + off);
    }
    #pragma unroll
    for (int it = 0; it < 8; it++) {
        int idx = tid + it * 256;
        int m = idx >> 4, kq = (idx & 15) * 4;
        float4 v;
        v.x = tanh_ap(pfi[it].x + pfh[it].x);
        v.y = tanh_ap(pfi[it].y + pfh[it].y);
        v.z = tanh_ap(pfi[it].z + pfh[it].z);
        v.w = tanh_ap(pfi[it].w + pfh[it].w);
        split_store(sA + m * HAP + kq, sA + HA_HL + m * HAP + kq, v);
    }
    __syncthreads();

    for (int c = 0; c < 4; c++) {
        const int cur = c & 1, nxt = cur ^ 1;

        if (c < 3) {
            #pragma unroll
            for (int it = 0; it < 8; it++) {
                int idx = tid + it * 256;
                int m = idx >> 4, kq = (idx & 15) * 4;
                size_t off = (size_t)(m0 + m) * HID + (c + 1) * 64 + kq;
                pfi[it] = *(const float4*)(i2h + off);
                pfh[it] = *(const float4*)(h2h + off);
            }
        }

        const uint32_t aHi = aB + cur * (HA_BUF * 2);
        const uint32_t aLo = aHi + HA_HL * 2;
        #pragma unroll
        for (int kk = 0; kk < 64; kk += 16) {
            uint32_t ah[2][4], al[2][4], bh[2][4], bl[2][4];
            #pragma unroll
            for (int mb = 0; mb < 2; mb++) {
                LDSM4(ah[mb], aHi + a_off[mb] + kk * 2);
                LDSM4(al[mb], aLo + a_off[mb] + kk * 2);
            }
            const uint32_t kb = (c * 64 + kk) * 2;
            #pragma unroll
            for (int nbp = 0; nbp < 2; nbp++) {
                LDSM4(bh[nbp], wHiB + b_off[nbp] + kb);
                LDSM4(bl[nbp], wLoB + b_off[nbp] + kb);
            }
            #pragma unroll
            for (int nb = 0; nb < 4; nb++)
                #pragma unroll
                for (int mb = 0; mb < 2; mb++)
                    MMA16816(acc[mb][nb], ah[mb], &bh[nb >> 1][(nb & 1) * 2]);
            #pragma unroll
            for (int nb = 0; nb < 4; nb++)
                #pragma unroll
                for (int mb = 0; mb < 2; mb++)
                    MMA16816(acc[mb][nb], ah[mb], &bl[nb >> 1][(nb & 1) * 2]);
            #pragma unroll
            for (int nb = 0; nb < 4; nb++)
                #pragma unroll
                for (int mb = 0; mb < 2; mb++)
                    MMA16816(acc[mb][nb], al[mb], &bh[nb >> 1][(nb & 1) * 2]);
        }

        if (c < 3) {
            #pragma unroll
            for (int it = 0; it < 8; it++) {
                int idx = tid + it * 256;
                int m = idx >> 4, kq = (idx & 15) * 4;
                float4 v;
                v.x = tanh_ap(pfi[it].x + pfh[it].x);
                v.y = tanh_ap(pfi[it].y + pfh[it].y);
                v.z = tanh_ap(pfi[it].z + pfh[it].z);
                v.w = tanh_ap(pfi[it].w + pfh[it].w);
                split_store(sA + nxt * HA_BUF + m * HAP + kq,
                            sA + nxt * HA_BUF + HA_HL + m * HAP + kq, v);
            }
            __syncthreads();
        }
    }

    // ---- O = tanh(acc + bo) -> smem (overlay A buffers) ----
    __syncthreads();
    float* Osm = (float*)sA;                   // [128][68] fp32
    #pragma unroll
    for (int mb = 0; mb < 2; mb++) {
        #pragma unroll
        for (int nb = 0; nb < 4; nb++) {
            int lr = mwb + mb * 16 + tq;
            int gc = nwb + nb * 8 + tr * 2;
            float2 bv = *(const float2*)(bo + gc);
            #pragma unroll
            for (int half = 0; half < 2; half++) {
                *(float2*)(Osm + (lr + half * 8) * 68 + gc) =
                    make_float2(tanh_ap(acc[mb][nb][half * 2 + 0] + bv.x),
                                tanh_ap(acc[mb][nb][half * 2 + 1] + bv.y));
            }
        }
    }
    __syncthreads();

    // ---- fcc: 128 rows x 8 classes ----
    #pragma unroll
    for (int i = 0; i < 4; i++) {
        int idx = tid + i * 256;
        int row = idx >> 3;
        int cc  = idx & 7;
        const float* orow = Osm + row * 68;
        const float* wr   = wf + cc * OUT_F;
        float s = bfs[cc];
        #pragma unroll
        for (int o = 0; o < OUT_F; o++) s += orow[o] * wr[o];
        outseq[(size_t)(m0 + row) * NCLS + cc] = s;
    }
}

// ============================================================================
extern "C" void kernel_launch(void* const* d_in, const int* in_sizes, int n_in,
                              void* d_out, int out_size)
{
    const float* x      = (const float*)d_in[0];
    const float* hc1    = (const float*)d_in[2];
    const float* hc2    = (const float*)d_in[3];
    const float* hc3    = (const float*)d_in[4];
    const float* hc4    = (const float*)d_in[5];
    const float* W_i2h  = (const float*)d_in[6];
    const float* b_i2h  = (const float*)d_in[7];
    const float* W_h2h  = (const float*)d_in[8];
    const float* b_h2h  = (const float*)d_in[9];
    const float* W_h2o  = (const float*)d_in[10];
    const float* b_h2o  = (const float*)d_in[11];
    const float* W_fcc  = (const float*)d_in[12];
    const float* b_fcc  = (const float*)d_in[13];

    float* out = (float*)d_out;
    float* i2h_seq = out + OFF_I2H;
    float* h2h_seq = out + OFF_H2H;

    cudaFuncSetAttribute(step_mma, cudaFuncAttributeMaxDynamicSharedMemorySize,
                         STEP_SMEM);
    cudaFuncSetAttribute(i2h_mma, cudaFuncAttributeMaxDynamicSharedMemorySize,
                         I2H_SMEM);
    cudaFuncSetAttribute(head_mma, cudaFuncAttributeMaxDynamicSharedMemorySize,
                         HEAD_SMEM);

    cudaMemcpyAsync(out + OFF_HC2, hc2, (size_t)SZ_HC * sizeof(float),
                    cudaMemcpyDeviceToDevice);
    cudaMemcpyAsync(out + OFF_HC3, hc3, (size_t)SZ_HC * sizeof(float),
                    cudaMemcpyDeviceToDevice);
    cudaMemcpyAsync(out + OFF_HC4, hc4, (size_t)SZ_HC * sizeof(float),
                    cudaMemcpyDeviceToDevice);

    // 0) split weights into bf16 hi/lo
    prep_w<<<256, 256>>>(W_h2h);
    prep_wi<<<64, 256>>>(W_i2h);
    prep_wo<<<64, 256>>>(W_h2o);

    // 1) i2h over all timesteps (tensor cores)
    dim3 g1(2, (T_STEPS * BATCH) / 128);
    i2h_mma<<<g1, 256, I2H_SMEM>>>(x, b_i2h, i2h_seq);

    // 2) sequential recurrence (tensor cores)
    dim3 g2(2, BATCH / 128);
    for (int t = 0; t < T_STEPS; t++) {
        step_mma<<<g2, 256, STEP_SMEM>>>(
            (t == 0) ? hc1 : nullptr,
            b_h2h,
            i2h_seq + (size_t)t * BATCH * HID,
            h2h_seq + (size_t)t * BATCH * HID,
            (t == T_STEPS - 1) ? (out + OFF_HC1) : nullptr);
    }

    // 3) output head (tensor cores + fused fcc)
    head_mma<<<(T_STEPS * BATCH) / 128, 256, HEAD_SMEM>>>(
        i2h_seq, h2h_seq, b_h2o, W_fcc, b_fcc, out + OFF_OUTSEQ);
}

// round 12
// speedup vs baseline: 2.2112x; 1.0945x over previous
#include <cuda_runtime.h>
#include <cuda_bf16.h>
#include <math.h>
#include <stdint.h>

#define T_STEPS 16
#define BATCH   8192
#define IN_F    64
#define HID     256
#define OUT_F   64
#define NCLS    8

// ---- d_out layout (floats), tuple flattened in reference-return order ----
#define SZ_OUTSEQ (T_STEPS*BATCH*NCLS)
#define SZ_HC     (BATCH*HID)
#define SZ_SEQ    (T_STEPS*BATCH*HID)
#define OFF_OUTSEQ 0
#define OFF_HC1   (OFF_OUTSEQ + SZ_OUTSEQ)
#define OFF_HC2   (OFF_HC1 + SZ_HC)
#define OFF_HC3   (OFF_HC2 + SZ_HC)
#define OFF_HC4   (OFF_HC3 + SZ_HC)
#define OFF_I2H   (OFF_HC4 + SZ_HC)
#define OFF_H2H   (OFF_I2H + SZ_SEQ)

#define STEP_CTAS 128

// ---------------- device scratch (no cudaMalloc allowed) ----------------
__device__ float g_h[BATCH * HID];                 // recurrent state (fp32)
__device__ __nv_bfloat16 g_Whi[HID * HID];         // W_h2h hi, [n][k]
__device__ __nv_bfloat16 g_Wlo[HID * HID];         // W_h2h lo
__device__ __nv_bfloat16 g_Wihi[HID * IN_F];       // W_i2h hi, [n][k]
__device__ __nv_bfloat16 g_Wilo[HID * IN_F];       // W_i2h lo
__device__ __nv_bfloat16 g_Wohi[OUT_F * HID];      // W_h2o hi, [n][k]
__device__ __nv_bfloat16 g_Wolo[OUT_F * HID];      // W_h2o lo
__device__ unsigned int g_bar[16];                 // grid-barrier counters
__device__ unsigned int g_zero16[16];              // never written: stays zero

__device__ __forceinline__ uint32_t pack2(__nv_bfloat16 a, __nv_bfloat16 b) {
    __nv_bfloat162 t; t.x = a; t.y = b;
    return *(uint32_t*)&t;
}
__device__ __forceinline__ uint32_t smem_u32(const void* p) {
    uint32_t a;
    asm("{ .reg .u64 t; cvta.to.shared.u64 t, %1; cvt.u32.u64 %0, t; }"
        : "=r"(a) : "l"(p));
    return a;
}
__device__ __forceinline__ float tanh_ap(float x) {
    float y;
    asm("tanh.approx.f32 %0, %1;" : "=f"(y) : "f"(x));
    return y;
}
__device__ __forceinline__ void split_store(__nv_bfloat16* hiDst,
                                            __nv_bfloat16* loDst, float4 v) {
    __nv_bfloat16 hx = __float2bfloat16(v.x);
    __nv_bfloat16 hy = __float2bfloat16(v.y);
    __nv_bfloat16 hz = __float2bfloat16(v.z);
    __nv_bfloat16 hw = __float2bfloat16(v.w);
    uint2 hv, lv;
    hv.x = pack2(hx, hy); hv.y = pack2(hz, hw);
    lv.x = pack2(__float2bfloat16(v.x - __bfloat162float(hx)),
                 __float2bfloat16(v.y - __bfloat162float(hy)));
    lv.y = pack2(__float2bfloat16(v.z - __bfloat162float(hz)),
                 __float2bfloat16(v.w - __bfloat162float(hw)));
    *(uint2*)hiDst = hv;
    *(uint2*)loDst = lv;
}

// All-CTA barrier (all CTAs resident: grid=128 <= 148 SMs, 1 CTA/SM).
__device__ __forceinline__ void grid_barrier(int i) {
    __syncthreads();
    if (threadIdx.x == 0) {
        asm volatile("red.release.gpu.global.add.u32 [%0], 1;"
                     :: "l"(&g_bar[i]) : "memory");
        unsigned int v;
        do {
            asm volatile("ld.acquire.gpu.global.b32 %0, [%1];"
                         : "=r"(v) : "l"(&g_bar[i]) : "memory");
        } while (v < STEP_CTAS);
    }
    __syncthreads();
}

// mma.sync m16n8k16 bf16 (baseline ISA)
#define MMA16816(c, a, b) \
    asm volatile("mma.sync.aligned.m16n8k16.row.col.f32.bf16.bf16.f32 " \
        "{%0,%1,%2,%3}, {%4,%5,%6,%7}, {%8,%9}, {%0,%1,%2,%3};" \
        : "+f"((c)[0]), "+f"((c)[1]), "+f"((c)[2]), "+f"((c)[3]) \
        : "r"((a)[0]), "r"((a)[1]), "r"((a)[2]), "r"((a)[3]), \
          "r"((b)[0]), "r"((b)[1]))

#define LDSM4(r, addr) \
    asm volatile("ldmatrix.sync.aligned.m8n8.x4.shared.b16 {%0,%1,%2,%3}, [%4];" \
        : "=r"((r)[0]), "=r"((r)[1]), "=r"((r)[2]), "=r"((r)[3]) : "r"(addr))

// ============================================================================
// prep kernels: split fp32 weights into bf16 hi/lo globals.
// ============================================================================
__global__ void prep_w(const float* __restrict__ W)
{
    int idx = blockIdx.x * 256 + threadIdx.x;
    float v = W[idx];
    __nv_bfloat16 hi = __float2bfloat16(v);
    g_Whi[idx] = hi;
    g_Wlo[idx] = __float2bfloat16(v - __bfloat162float(hi));
}
__global__ void prep_wi(const float* __restrict__ W)
{
    int idx = blockIdx.x * 256 + threadIdx.x;
    float v = W[idx];
    __nv_bfloat16 hi = __float2bfloat16(v);
    g_Wihi[idx] = hi;
    g_Wilo[idx] = __float2bfloat16(v - __bfloat162float(hi));
}
__global__ void prep_wo(const float* __restrict__ W)
{
    int idx = blockIdx.x * 256 + threadIdx.x;
    float v = W[idx];
    __nv_bfloat16 hi = __float2bfloat16(v);
    g_Wohi[idx] = hi;
    g_Wolo[idx] = __float2bfloat16(v - __bfloat162float(hi));
}

// ============================================================================
// step_fused: ALL 16 recurrence steps in one persistent kernel.
// Grid = 128 CTAs (2 n-tiles x 64 m-tiles), all resident; W smem-loaded ONCE.
// Inter-step ordering via grid_barrier (counters zeroed per launch by D2D copy).
// Per step: h2h = A @ W^T + b; h_new = tanh(i2h_t + h2h).
// ============================================================================
#define WPITCH 264
#define APITCH 72
#define W_HALF_ELEMS (128 * WPITCH)
#define A_HL_ELEMS   (128 * APITCH)
#define A_BUF_ELEMS  (2 * A_HL_ELEMS)
#define A_BASE_ELEMS (2 * W_HALF_ELEMS)
#define STEP_SMEM ((A_BASE_ELEMS + 2 * A_BUF_ELEMS) * 2)

__global__ __launch_bounds__(256, 1)
void step_fused(const float* __restrict__ hc1_in,
                const float* __restrict__ bias,
                const float* __restrict__ i2h_seq,
                float* __restrict__ h2h_seq,
                float* __restrict__ hc1f)
{
    extern __shared__ __nv_bfloat16 sm[];
    __nv_bfloat16* sWhi = sm;
    __nv_bfloat16* sWlo = sm + W_HALF_ELEMS;
    __nv_bfloat16* sA   = sm + A_BASE_ELEMS;

    const int tid = threadIdx.x;
    const int bid = blockIdx.x;
    const int n0 = (bid & 1) * 128;
    const int m0 = (bid >> 1) * 128;

    // ---- load W half ONCE (covers all 16 steps) ----
    #pragma unroll
    for (int i = tid; i < 4096; i += 256) {
        int n = i >> 5;
        int k8 = (i & 31) * 8;
        *(uint4*)(sWhi + n * WPITCH + k8) =
            *(const uint4*)(g_Whi + (size_t)(n0 + n) * HID + k8);
        *(uint4*)(sWlo + n * WPITCH + k8) =
            *(const uint4*)(g_Wlo + (size_t)(n0 + n) * HID + k8);
    }

    const int w = tid >> 5, lane = tid & 31;
    const int mwb = (w >> 1) * 32;
    const int nwb = (w & 1) * 64;
    const int tq = lane >> 2, tr = lane & 3;
    const int quad = lane >> 3, rl = lane & 7;

    uint32_t a_off[2], b_off[4];
    #pragma unroll
    for (int mb = 0; mb < 2; mb++)
        a_off[mb] = (uint32_t)(((mwb + mb * 16 + rl + (quad & 1) * 8) * APITCH
                                + (quad >> 1) * 8) * 2);
    #pragma unroll
    for (int nbp = 0; nbp < 4; nbp++)
        b_off[nbp] = (uint32_t)(((nwb + (nbp * 2 + (quad >> 1)) * 8 + rl) * WPITCH
                                 + (quad & 1) * 8) * 2);

    const uint32_t smb  = smem_u32(sm);
    const uint32_t wHiB = smb;
    const uint32_t wLoB = smb + W_HALF_ELEMS * 2;
    const uint32_t aB   = smb + A_BASE_ELEMS * 2;

    for (int t = 0; t < T_STEPS; t++) {
        const float* __restrict__ A = (t == 0) ? hc1_in : g_h;
        const float* __restrict__ i2h_t = i2h_seq + (size_t)t * SZ_HC;
        float* __restrict__ h2h_out = h2h_seq + (size_t)t * SZ_HC;

        float acc[2][8][4];
        #pragma unroll
        for (int mb = 0; mb < 2; mb++)
            #pragma unroll
            for (int nb = 0; nb < 8; nb++)
                #pragma unroll
                for (int q = 0; q < 4; q++) acc[mb][nb][q] = 0.f;

        float4 pf[8];
        #pragma unroll
        for (int it = 0; it < 8; it++) {
            int idx = tid + it * 256;
            int m = idx >> 4, kq = (idx & 15) * 4;
            pf[it] = *(const float4*)(A + (size_t)(m0 + m) * HID + kq);
        }
        #pragma unroll
        for (int it = 0; it < 8; it++) {
            int idx = tid + it * 256;
            int m = idx >> 4, kq = (idx & 15) * 4;
            split_store(sA + m * APITCH + kq,
                        sA + A_HL_ELEMS + m * APITCH + kq, pf[it]);
        }
        __syncthreads();

        for (int c = 0; c < 4; c++) {
            const int cur = c & 1, nxt = cur ^ 1;

            if (c < 3) {
                #pragma unroll
                for (int it = 0; it < 8; it++) {
                    int idx = tid + it * 256;
                    int m = idx >> 4, kq = (idx & 15) * 4;
                    pf[it] = *(const float4*)(A + (size_t)(m0 + m) * HID
                                              + (c + 1) * 64 + kq);
                }
            }

            const uint32_t aHi = aB + cur * (A_BUF_ELEMS * 2);
            const uint32_t aLo = aHi + A_HL_ELEMS * 2;
            #pragma unroll
            for (int kk = 0; kk < 64; kk += 16) {
                uint32_t ah[2][4], al[2][4], bh[4][4], bl[4][4];
                #pragma unroll
                for (int mb = 0; mb < 2; mb++) {
                    LDSM4(ah[mb], aHi + a_off[mb] + kk * 2);
                    LDSM4(al[mb], aLo + a_off[mb] + kk * 2);
                }
                const uint32_t kb = (c * 64 + kk) * 2;
                #pragma unroll
                for (int nbp = 0; nbp < 4; nbp++) {
                    LDSM4(bh[nbp], wHiB + b_off[nbp] + kb);
                    LDSM4(bl[nbp], wLoB + b_off[nbp] + kb);
                }
                #pragma unroll
                for (int nb = 0; nb < 8; nb++)
                    #pragma unroll
                    for (int mb = 0; mb < 2; mb++)
                        MMA16816(acc[mb][nb], ah[mb], &bh[nb >> 1][(nb & 1) * 2]);
                #pragma unroll
                for (int nb = 0; nb < 8; nb++)
                    #pragma unroll
                    for (int mb = 0; mb < 2; mb++)
                        MMA16816(acc[mb][nb], ah[mb], &bl[nb >> 1][(nb & 1) * 2]);
                #pragma unroll
                for (int nb = 0; nb < 8; nb++)
                    #pragma unroll
                    for (int mb = 0; mb < 2; mb++)
                        MMA16816(acc[mb][nb], al[mb], &bh[nb >> 1][(nb & 1) * 2]);
            }

            if (c < 3) {
                #pragma unroll
                for (int it = 0; it < 8; it++) {
                    int idx = tid + it * 256;
                    int m = idx >> 4, kq = (idx & 15) * 4;
                    split_store(sA + nxt * A_BUF_ELEMS + m * APITCH + kq,
                                sA + nxt * A_BUF_ELEMS + A_HL_ELEMS + m * APITCH + kq,
                                pf[it]);
                }
                __syncthreads();
            }
        }

        // ---- epilogue ----
        #pragma unroll
        for (int mb = 0; mb < 2; mb++) {
            #pragma unroll
            for (int nb = 0; nb < 8; nb++) {
                int gr = m0 + mwb + mb * 16 + tq;
                int gc = n0 + nwb + nb * 8 + tr * 2;
                float2 bv = *(const float2*)(bias + gc);
                #pragma unroll
                for (int half = 0; half < 2; half++) {
                    int r = gr + half * 8;
                    float p0 = acc[mb][nb][half * 2 + 0] + bv.x;
                    float p1 = acc[mb][nb][half * 2 + 1] + bv.y;
                    size_t off = (size_t)r * HID + gc;
                    *(float2*)(h2h_out + off) = make_float2(p0, p1);
                    float2 iv = *(const float2*)(i2h_t + off);
                    float2 hn = make_float2(tanh_ap(iv.x + p0),
                                            tanh_ap(iv.y + p1));
                    *(float2*)(g_h + off) = hn;
                    if (t == T_STEPS - 1)
                        *(float2*)(hc1f + off) = hn;
                }
            }
        }

        if (t < T_STEPS - 1) grid_barrier(t);
    }
}

// ============================================================================
// i2h_mma: C = X @ W_i2h^T + b.  M=131072, N=256, K=64.
// launch_bounds(256,2): cap regs at 128 -> 2 CTAs/SM (smem 72KB each).
// ============================================================================
#define IAP 72
#define I2H_SMEM (4 * 128 * IAP * 2)

__global__ __launch_bounds__(256, 2)
void i2h_mma(const float* __restrict__ X,
             const float* __restrict__ bias,
             float* __restrict__ C)
{
    extern __shared__ __nv_bfloat16 ism[];
    __nv_bfloat16* sWhi = ism;
    __nv_bfloat16* sWlo = sWhi + 128 * IAP;
    __nv_bfloat16* sAhi = sWlo + 128 * IAP;
    __nv_bfloat16* sAlo = sAhi + 128 * IAP;

    const int tid = threadIdx.x;
    const int n0 = blockIdx.x * 128;
    const int m0 = blockIdx.y * 128;

    #pragma unroll
    for (int i = tid; i < 1024; i += 256) {
        int n = i >> 3, k8 = (i & 7) * 8;
        *(uint4*)(sWhi + n * IAP + k8) =
            *(const uint4*)(g_Wihi + (size_t)(n0 + n) * IN_F + k8);
        *(uint4*)(sWlo + n * IAP + k8) =
            *(const uint4*)(g_Wilo + (size_t)(n0 + n) * IN_F + k8);
    }
    #pragma unroll
    for (int it = 0; it < 8; it++) {
        int idx = tid + it * 256;
        int m = idx >> 4, kq = (idx & 15) * 4;
        float4 v = *(const float4*)(X + (size_t)(m0 + m) * IN_F + kq);
        split_store(sAhi + m * IAP + kq, sAlo + m * IAP + kq, v);
    }
    __syncthreads();

    const int w = tid >> 5, lane = tid & 31;
    const int mwb = (w >> 1) * 32;
    const int nwb = (w & 1) * 64;
    const int tq = lane >> 2, tr = lane & 3;
    const int quad = lane >> 3, rl = lane & 7;

    uint32_t a_off[2], b_off[4];
    #pragma unroll
    for (int mb = 0; mb < 2; mb++)
        a_off[mb] = (uint32_t)(((mwb + mb * 16 + rl + (quad & 1) * 8) * IAP
                                + (quad >> 1) * 8) * 2);
    #pragma unroll
    for (int nbp = 0; nbp < 4; nbp++)
        b_off[nbp] = (uint32_t)(((nwb + (nbp * 2 + (quad >> 1)) * 8 + rl) * IAP
                                 + (quad & 1) * 8) * 2);

    const uint32_t smb = smem_u32(ism);
    const uint32_t wHiB = smb;
    const uint32_t wLoB = smb + 128 * IAP * 2;
    const uint32_t aHiB = smb + 2 * 128 * IAP * 2;
    const uint32_t aLoB = smb + 3 * 128 * IAP * 2;

    float acc[2][8][4];
    #pragma unroll
    for (int mb = 0; mb < 2; mb++)
        #pragma unroll
        for (int nb = 0; nb < 8; nb++)
            #pragma unroll
            for (int q = 0; q < 4; q++) acc[mb][nb][q] = 0.f;

    #pragma unroll
    for (int kk = 0; kk < 64; kk += 16) {
        uint32_t ah[2][4], al[2][4], bh[4][4], bl[4][4];
        #pragma unroll
        for (int mb = 0; mb < 2; mb++) {
            LDSM4(ah[mb], aHiB + a_off[mb] + kk * 2);
            LDSM4(al[mb], aLoB + a_off[mb] + kk * 2);
        }
        #pragma unroll
        for (int nbp = 0; nbp < 4; nbp++) {
            LDSM4(bh[nbp], wHiB + b_off[nbp] + kk * 2);
            LDSM4(bl[nbp], wLoB + b_off[nbp] + kk * 2);
        }
        #pragma unroll
        for (int nb = 0; nb < 8; nb++)
            #pragma unroll
            for (int mb = 0; mb < 2; mb++)
                MMA16816(acc[mb][nb], ah[mb], &bh[nb >> 1][(nb & 1) * 2]);
        #pragma unroll
        for (int nb = 0; nb < 8; nb++)
            #pragma unroll
            for (int mb = 0; mb < 2; mb++)
                MMA16816(acc[mb][nb], ah[mb], &bl[nb >> 1][(nb & 1) * 2]);
        #pragma unroll
        for (int nb = 0; nb < 8; nb++)
            #pragma unroll
            for (int mb = 0; mb < 2; mb++)
                MMA16816(acc[mb][nb], al[mb], &bh[nb >> 1][(nb & 1) * 2]);
    }

    #pragma unroll
    for (int mb = 0; mb < 2; mb++) {
        #pragma unroll
        for (int nb = 0; nb < 8; nb++) {
            int gr = m0 + mwb + mb * 16 + tq;
            int gc = n0 + nwb + nb * 8 + tr * 2;
            float2 bv = *(const float2*)(bias + gc);
            #pragma unroll
            for (int half = 0; half < 2; half++) {
                size_t off = (size_t)(gr + half * 8) * HID + gc;
                *(float2*)(C + off) =
                    make_float2(acc[mb][nb][half * 2 + 0] + bv.x,
                                acc[mb][nb][half * 2 + 1] + bv.y);
            }
        }
    }
}

// ============================================================================
// head_mma (unchanged from R11)
// ============================================================================
#define HWP 264
#define HAP 72
#define HW_ELEMS (64 * HWP)
#define HA_HL   (128 * HAP)
#define HA_BUF  (2 * HA_HL)
#define HA_BASE (2 * HW_ELEMS)
#define HEAD_SMEM ((HA_BASE + 2 * HA_BUF) * 2)

__global__ __launch_bounds__(256, 1)
void head_mma(const float* __restrict__ i2h, const float* __restrict__ h2h,
              const float* __restrict__ bo,
              const float* __restrict__ Wf, const float* __restrict__ bf,
              float* __restrict__ outseq)
{
    extern __shared__ __nv_bfloat16 hsm[];
    __nv_bfloat16* sWhi = hsm;
    __nv_bfloat16* sWlo = hsm + HW_ELEMS;
    __nv_bfloat16* sA   = hsm + HA_BASE;
    __shared__ float wf[NCLS * OUT_F];
    __shared__ float bfs[NCLS];

    const int tid = threadIdx.x;
    const int m0 = blockIdx.x * 128;

    wf[tid]       = Wf[tid];
    wf[tid + 256] = Wf[tid + 256];
    if (tid < NCLS) bfs[tid] = bf[tid];

    #pragma unroll
    for (int i = tid; i < 2048; i += 256) {
        int n = i >> 5, k8 = (i & 31) * 8;
        *(uint4*)(sWhi + n * HWP + k8) =
            *(const uint4*)(g_Wohi + (size_t)n * HID + k8);
        *(uint4*)(sWlo + n * HWP + k8) =
            *(const uint4*)(g_Wolo + (size_t)n * HID + k8);
    }

    const int w = tid >> 5, lane = tid & 31;
    const int mwb = (w >> 1) * 32;
    const int nwb = (w & 1) * 32;
    const int tq = lane >> 2, tr = lane & 3;
    const int quad = lane >> 3, rl = lane & 7;

    uint32_t a_off[2], b_off[2];
    #pragma unroll
    for (int mb = 0; mb < 2; mb++)
        a_off[mb] = (uint32_t)(((mwb + mb * 16 + rl + (quad & 1) * 8) * HAP
                                + (quad >> 1) * 8) * 2);
    #pragma unroll
    for (int nbp = 0; nbp < 2; nbp++)
        b_off[nbp] = (uint32_t)(((nwb + (nbp * 2 + (quad >> 1)) * 8 + rl) * HWP
                                 + (quad & 1) * 8) * 2);

    const uint32_t smb = smem_u32(hsm);
    const uint32_t wHiB = smb;
    const uint32_t wLoB = smb + HW_ELEMS * 2;
    const uint32_t aB   = smb + HA_BASE * 2;

    float acc[2][4][4];
    #pragma unroll
    for (int mb = 0; mb < 2; mb++)
        #pragma unroll
        for (int nb = 0; nb < 4; nb++)
            #pragma unroll
            for (int q = 0; q < 4; q++) acc[mb][nb][q] = 0.f;

    float4 pfi[8], pfh[8];
    #pragma unroll
    for (int it = 0; it < 8; it++) {
        int idx = tid + it * 256;
        int m = idx >> 4, kq = (idx & 15) * 4;
        size_t off = (size_t)(m0 + m) * HID + kq;
        pfi[it] = *(const float4*)(i2h + off);
        pfh[it] = *(const float4*)(h2h + off);
    }
    #pragma unroll
    for (int it = 0; it < 8; it++) {
        int idx = tid + it * 256;
        int m = idx >> 4, kq = (idx & 15) * 4;
        float4 v;
        v.x = tanh_ap(pfi[it].x + pfh[it].x);
        v.y = tanh_ap(pfi[it].y + pfh[it].y);
        v.z = tanh_ap(pfi[it].z + pfh[it].z);
        v.w = tanh_ap(pfi[it].w + pfh[it].w);
        split_store(sA + m * HAP + kq, sA + HA_HL + m * HAP + kq, v);
    }
    __syncthreads();

    for (int c = 0; c < 4; c++) {
        const int cur = c & 1, nxt = cur ^ 1;

        if (c < 3) {
            #pragma unroll
            for (int it = 0; it < 8; it++) {
                int idx = tid + it * 256;
                int m = idx >> 4, kq = (idx & 15) * 4;
                size_t off = (size_t)(m0 + m) * HID + (c + 1) * 64 + kq;
                pfi[it] = *(const float4*)(i2h + off);
                pfh[it] = *(const float4*)(h2h + off);
            }
        }

        const uint32_t aHi = aB + cur * (HA_BUF * 2);
        const uint32_t aLo = aHi + HA_HL * 2;
        #pragma unroll
        for (int kk = 0; kk < 64; kk += 16) {
            uint32_t ah[2][4], al[2][4], bh[2][4], bl[2][4];
            #pragma unroll
            for (int mb = 0; mb < 2; mb++) {
                LDSM4(ah[mb], aHi + a_off[mb] + kk * 2);
                LDSM4(al[mb], aLo + a_off[mb] + kk * 2);
            }
            const uint32_t kb = (c * 64 + kk) * 2;
            #pragma unroll
            for (int nbp = 0; nbp < 2; nbp++) {
                LDSM4(bh[nbp], wHiB + b_off[nbp] + kb);
                LDSM4(bl[nbp], wLoB + b_off[nbp] + kb);
            }
            #pragma unroll
            for (int nb = 0; nb < 4; nb++)
                #pragma unroll
                for (int mb = 0; mb < 2; mb++)
                    MMA16816(acc[mb][nb], ah[mb], &bh[nb >> 1][(nb & 1) * 2]);
            #pragma unroll
            for (int nb = 0; nb < 4; nb++)
                #pragma unroll
                for (int mb = 0; mb < 2; mb++)
                    MMA16816(acc[mb][nb], ah[mb], &bl[nb >> 1][(nb & 1) * 2]);
            #pragma unroll
            for (int nb = 0; nb < 4; nb++)
                #pragma unroll
                for (int mb = 0; mb < 2; mb++)
                    MMA16816(acc[mb][nb], al[mb], &bh[nb >> 1][(nb & 1) * 2]);
        }

        if (c < 3) {
            #pragma unroll
            for (int it = 0; it < 8; it++) {
                int idx = tid + it * 256;
                int m = idx >> 4, kq = (idx & 15) * 4;
                float4 v;
                v.x = tanh_ap(pfi[it].x + pfh[it].x);
                v.y = tanh_ap(pfi[it].y + pfh[it].y);
                v.z = tanh_ap(pfi[it].z + pfh[it].z);
                v.w = tanh_ap(pfi[it].w + pfh[it].w);
                split_store(sA + nxt * HA_BUF + m * HAP + kq,
                            sA + nxt * HA_BUF + HA_HL + m * HAP + kq, v);
            }
            __syncthreads();
        }
    }

    __syncthreads();
    float* Osm = (float*)sA;
    #pragma unroll
    for (int mb = 0; mb < 2; mb++) {
        #pragma unroll
        for (int nb = 0; nb < 4; nb++) {
            int lr = mwb + mb * 16 + tq;
            int gc = nwb + nb * 8 + tr * 2;
            float2 bv = *(const float2*)(bo + gc);
            #pragma unroll
            for (int half = 0; half < 2; half++) {
                *(float2*)(Osm + (lr + half * 8) * 68 + gc) =
                    make_float2(tanh_ap(acc[mb][nb][half * 2 + 0] + bv.x),
                                tanh_ap(acc[mb][nb][half * 2 + 1] + bv.y));
            }
        }
    }
    __syncthreads();

    #pragma unroll
    for (int i = 0; i < 4; i++) {
        int idx = tid + i * 256;
        int row = idx >> 3;
        int cc  = idx & 7;
        const float* orow = Osm + row * 68;
        const float* wr   = wf + cc * OUT_F;
        float s = bfs[cc];
        #pragma unroll
        for (int o = 0; o < OUT_F; o++) s += orow[o] * wr[o];
        outseq[(size_t)(m0 + row) * NCLS + cc] = s;
    }
}

// ============================================================================
extern "C" void kernel_launch(void* const* d_in, const int* in_sizes, int n_in,
                              void* d_out, int out_size)
{
    const float* x      = (const float*)d_in[0];
    const float* hc1    = (const float*)d_in[2];
    const float* hc2    = (const float*)d_in[3];
    const float* hc3    = (const float*)d_in[4];
    const float* hc4    = (const float*)d_in[5];
    const float* W_i2h  = (const float*)d_in[6];
    const float* b_i2h  = (const float*)d_in[7];
    const float* W_h2h  = (const float*)d_in[8];
    const float* b_h2h  = (const float*)d_in[9];
    const float* W_h2o  = (const float*)d_in[10];
    const float* b_h2o  = (const float*)d_in[11];
    const float* W_fcc  = (const float*)d_in[12];
    const float* b_fcc  = (const float*)d_in[13];

    float* out = (float*)d_out;
    float* i2h_seq = out + OFF_I2H;
    float* h2h_seq = out + OFF_H2H;

    cudaFuncSetAttribute(step_fused, cudaFuncAttributeMaxDynamicSharedMemorySize,
                         STEP_SMEM);
    cudaFuncSetAttribute(i2h_mma, cudaFuncAttributeMaxDynamicSharedMemorySize,
                         I2H_SMEM);
    cudaFuncSetAttribute(head_mma, cudaFuncAttributeMaxDynamicSharedMemorySize,
                         HEAD_SMEM);

    cudaMemcpyAsync(out + OFF_HC2, hc2, (size_t)SZ_HC * sizeof(float),
                    cudaMemcpyDeviceToDevice);
    cudaMemcpyAsync(out + OFF_HC3, hc3, (size_t)SZ_HC * sizeof(float),
                    cudaMemcpyDeviceToDevice);
    cudaMemcpyAsync(out + OFF_HC4, hc4, (size_t)SZ_HC * sizeof(float),
                    cudaMemcpyDeviceToDevice);

    // reset grid-barrier counters (D2D copy from never-written zero symbol)
    void* bar_ptr = nullptr;
    void* zero_ptr = nullptr;
    cudaGetSymbolAddress(&bar_ptr, g_bar);
    cudaGetSymbolAddress(&zero_ptr, g_zero16);
    cudaMemcpyAsync(bar_ptr, zero_ptr, 16 * sizeof(unsigned int),
                    cudaMemcpyDeviceToDevice);

    // 0) split weights into bf16 hi/lo
    prep_w<<<256, 256>>>(W_h2h);
    prep_wi<<<64, 256>>>(W_i2h);
    prep_wo<<<64, 256>>>(W_h2o);

    // 1) i2h over all timesteps (tensor cores, 2 CTAs/SM)
    dim3 g1(2, (T_STEPS * BATCH) / 128);
    i2h_mma<<<g1, 256, I2H_SMEM>>>(x, b_i2h, i2h_seq);

    // 2) ALL 16 recurrence steps in one persistent kernel
    step_fused<<<STEP_CTAS, 256, STEP_SMEM>>>(
        hc1, b_h2h, i2h_seq, h2h_seq, out + OFF_HC1);

    // 3) output head (tensor cores + fused fcc)
    head_mma<<<(T_STEPS * BATCH) / 128, 256, HEAD_SMEM>>>(
        i2h_seq, h2h_seq, b_h2o, W_fcc, b_fcc, out + OFF_OUTSEQ);
}

// round 14
// speedup vs baseline: 2.3865x; 1.0793x over previous
#include <cuda_runtime.h>
#include <cuda_bf16.h>
#include <math.h>
#include <stdint.h>

#define T_STEPS 16
#define BATCH   8192
#define IN_F    64
#define HID     256
#define OUT_F   64
#define NCLS    8

// ---- d_out layout (floats), tuple flattened in reference-return order ----
#define SZ_OUTSEQ (T_STEPS*BATCH*NCLS)
#define SZ_HC     (BATCH*HID)
#define SZ_SEQ    (T_STEPS*BATCH*HID)
#define OFF_OUTSEQ 0
#define OFF_HC1   (OFF_OUTSEQ + SZ_OUTSEQ)
#define OFF_HC2   (OFF_HC1 + SZ_HC)
#define OFF_HC3   (OFF_HC2 + SZ_HC)
#define OFF_HC4   (OFF_HC3 + SZ_HC)
#define OFF_I2H   (OFF_HC4 + SZ_HC)
#define OFF_H2H   (OFF_I2H + SZ_SEQ)

#define STEP_CTAS 128

// ---------------- device scratch (no cudaMalloc allowed) ----------------
__device__ float g_hh[2][BATCH * HID];             // double-buffered h state
__device__ __nv_bfloat16 g_Whi[HID * HID];         // W_h2h hi, [n][k]
__device__ __nv_bfloat16 g_Wlo[HID * HID];         // W_h2h lo
__device__ __nv_bfloat16 g_Wihi[HID * IN_F];       // W_i2h hi, [n][k]
__device__ __nv_bfloat16 g_Wilo[HID * IN_F];       // W_i2h lo
__device__ __nv_bfloat16 g_Wohi[OUT_F * HID];      // W_h2o hi, [n][k]
__device__ __nv_bfloat16 g_Wolo[OUT_F * HID];      // W_h2o lo

__device__ __forceinline__ uint32_t pack2(__nv_bfloat16 a, __nv_bfloat16 b) {
    __nv_bfloat162 t; t.x = a; t.y = b;
    return *(uint32_t*)&t;
}
__device__ __forceinline__ uint32_t smem_u32(const void* p) {
    uint32_t a;
    asm("{ .reg .u64 t; cvta.to.shared.u64 t, %1; cvt.u32.u64 %0, t; }"
        : "=r"(a) : "l"(p));
    return a;
}
__device__ __forceinline__ float tanh_ap(float x) {
    float y;
    asm("tanh.approx.f32 %0, %1;" : "=f"(y) : "f"(x));
    return y;
}
__device__ __forceinline__ void split_store(__nv_bfloat16* hiDst,
                                            __nv_bfloat16* loDst, float4 v) {
    __nv_bfloat16 hx = __float2bfloat16(v.x);
    __nv_bfloat16 hy = __float2bfloat16(v.y);
    __nv_bfloat16 hz = __float2bfloat16(v.z);
    __nv_bfloat16 hw = __float2bfloat16(v.w);
    uint2 hv, lv;
    hv.x = pack2(hx, hy); hv.y = pack2(hz, hw);
    lv.x = pack2(__float2bfloat16(v.x - __bfloat162float(hx)),
                 __float2bfloat16(v.y - __bfloat162float(hy)));
    lv.y = pack2(__float2bfloat16(v.z - __bfloat162float(hz)),
                 __float2bfloat16(v.w - __bfloat162float(hw)));
    *(uint2*)hiDst = hv;
    *(uint2*)loDst = lv;
}

#define CLUSTER_SYNC() do { \
    asm volatile("barrier.cluster.arrive.aligned;" ::: "memory"); \
    asm volatile("barrier.cluster.wait.aligned;" ::: "memory"); \
} while (0)

// mma.sync m16n8k16 bf16 (baseline ISA)
#define MMA16816(c, a, b) \
    asm volatile("mma.sync.aligned.m16n8k16.row.col.f32.bf16.bf16.f32 " \
        "{%0,%1,%2,%3}, {%4,%5,%6,%7}, {%8,%9}, {%0,%1,%2,%3};" \
        : "+f"((c)[0]), "+f"((c)[1]), "+f"((c)[2]), "+f"((c)[3]) \
        : "r"((a)[0]), "r"((a)[1]), "r"((a)[2]), "r"((a)[3]), \
          "r"((b)[0]), "r"((b)[1]))

#define LDSM4(r, addr) \
    asm volatile("ldmatrix.sync.aligned.m8n8.x4.shared.b16 {%0,%1,%2,%3}, [%4];" \
        : "=r"((r)[0]), "=r"((r)[1]), "=r"((r)[2]), "=r"((r)[3]) : "r"(addr))

// ============================================================================
// prep kernels: split fp32 weights into bf16 hi/lo globals.
// ============================================================================
__global__ void prep_w(const float* __restrict__ W)
{
    int idx = blockIdx.x * 256 + threadIdx.x;
    float v = W[idx];
    __nv_bfloat16 hi = __float2bfloat16(v);
    g_Whi[idx] = hi;
    g_Wlo[idx] = __float2bfloat16(v - __bfloat162float(hi));
}
__global__ void prep_wi(const float* __restrict__ W)
{
    int idx = blockIdx.x * 256 + threadIdx.x;
    float v = W[idx];
    __nv_bfloat16 hi = __float2bfloat16(v);
    g_Wihi[idx] = hi;
    g_Wilo[idx] = __float2bfloat16(v - __bfloat162float(hi));
}
__global__ void prep_wo(const float* __restrict__ W)
{
    int idx = blockIdx.x * 256 + threadIdx.x;
    float v = W[idx];
    __nv_bfloat16 hi = __float2bfloat16(v);
    g_Wohi[idx] = hi;
    g_Wolo[idx] = __float2bfloat16(v - __bfloat162float(hi));
}

// ============================================================================
// step_fused: ALL 16 recurrence steps, persistent, 2-CTA clusters.
// Cluster = {CTA(m,0), CTA(m,1)} covering rows m x full N=256; the only
// cross-CTA dependency is within the pair -> barrier.cluster per step.
// 512 threads = 16 warps (4m x 4n), warp tile 32m x 32n.
// h state double-buffered in g_hh (no cross-step WAR).
// ============================================================================
#define WPITCH 264
#define APITCH 72
#define W_HALF_ELEMS (128 * WPITCH)
#define A_HL_ELEMS   (128 * APITCH)
#define A_BUF_ELEMS  (2 * A_HL_ELEMS)
#define A_BASE_ELEMS (2 * W_HALF_ELEMS)
#define STEP_SMEM ((A_BASE_ELEMS + 2 * A_BUF_ELEMS) * 2)

__global__ __launch_bounds__(512, 1) __cluster_dims__(2, 1, 1)
void step_fused(const float* __restrict__ hc1_in,
                const float* __restrict__ bias,
                const float* __restrict__ i2h_seq,
                float* __restrict__ h2h_seq,
                float* __restrict__ hc1f)
{
    extern __shared__ __nv_bfloat16 sm[];
    __nv_bfloat16* sWhi = sm;
    __nv_bfloat16* sWlo = sm + W_HALF_ELEMS;
    __nv_bfloat16* sA   = sm + A_BASE_ELEMS;

    const int tid = threadIdx.x;
    const int bid = blockIdx.x;
    const int n0 = (bid & 1) * 128;
    const int m0 = (bid >> 1) * 128;

    // ---- load W half ONCE (covers all 16 steps) ----
    #pragma unroll
    for (int i = tid; i < 4096; i += 512) {
        int n = i >> 5;
        int k8 = (i & 31) * 8;
        *(uint4*)(sWhi + n * WPITCH + k8) =
            *(const uint4*)(g_Whi + (size_t)(n0 + n) * HID + k8);
        *(uint4*)(sWlo + n * WPITCH + k8) =
            *(const uint4*)(g_Wlo + (size_t)(n0 + n) * HID + k8);
    }

    const int w = tid >> 5, lane = tid & 31;
    const int mwb = (w >> 2) * 32;      // 4 m-warp rows
    const int nwb = (w & 3) * 32;       // 4 n-warp cols
    const int tq = lane >> 2, tr = lane & 3;
    const int quad = lane >> 3, rl = lane & 7;

    uint32_t a_off[2], b_off[2];
    #pragma unroll
    for (int mb = 0; mb < 2; mb++)
        a_off[mb] = (uint32_t)(((mwb + mb * 16 + rl + (quad & 1) * 8) * APITCH
                                + (quad >> 1) * 8) * 2);
    #pragma unroll
    for (int nbp = 0; nbp < 2; nbp++)
        b_off[nbp] = (uint32_t)(((nwb + (nbp * 2 + (quad >> 1)) * 8 + rl) * WPITCH
                                 + (quad & 1) * 8) * 2);

    const uint32_t smb  = smem_u32(sm);
    const uint32_t wHiB = smb;
    const uint32_t wLoB = smb + W_HALF_ELEMS * 2;
    const uint32_t aB   = smb + A_BASE_ELEMS * 2;

    for (int t = 0; t < T_STEPS; t++) {
        const float* __restrict__ A =
            (t == 0) ? hc1_in : g_hh[(t - 1) & 1];
        float* __restrict__ Hn = g_hh[t & 1];
        const float* __restrict__ i2h_t = i2h_seq + (size_t)t * SZ_HC;
        float* __restrict__ h2h_out = h2h_seq + (size_t)t * SZ_HC;

        float acc[2][4][4];
        #pragma unroll
        for (int mb = 0; mb < 2; mb++)
            #pragma unroll
            for (int nb = 0; nb < 4; nb++)
                #pragma unroll
                for (int q = 0; q < 4; q++) acc[mb][nb][q] = 0.f;

        float4 pf[4];
        #pragma unroll
        for (int it = 0; it < 4; it++) {
            int idx = tid + it * 512;
            int m = idx >> 4, kq = (idx & 15) * 4;
            pf[it] = *(const float4*)(A + (size_t)(m0 + m) * HID + kq);
        }
        #pragma unroll
        for (int it = 0; it < 4; it++) {
            int idx = tid + it * 512;
            int m = idx >> 4, kq = (idx & 15) * 4;
            split_store(sA + m * APITCH + kq,
                        sA + A_HL_ELEMS + m * APITCH + kq, pf[it]);
        }
        __syncthreads();

        for (int c = 0; c < 4; c++) {
            const int cur = c & 1, nxt = cur ^ 1;

            if (c < 3) {
                #pragma unroll
                for (int it = 0; it < 4; it++) {
                    int idx = tid + it * 512;
                    int m = idx >> 4, kq = (idx & 15) * 4;
                    pf[it] = *(const float4*)(A + (size_t)(m0 + m) * HID
                                              + (c + 1) * 64 + kq);
                }
            }

            const uint32_t aHi = aB + cur * (A_BUF_ELEMS * 2);
            const uint32_t aLo = aHi + A_HL_ELEMS * 2;
            #pragma unroll
            for (int kk = 0; kk < 64; kk += 16) {
                uint32_t ah[2][4], al[2][4], bh[2][4], bl[2][4];
                #pragma unroll
                for (int mb = 0; mb < 2; mb++) {
                    LDSM4(ah[mb], aHi + a_off[mb] + kk * 2);
                    LDSM4(al[mb], aLo + a_off[mb] + kk * 2);
                }
                const uint32_t kb = (c * 64 + kk) * 2;
                #pragma unroll
                for (int nbp = 0; nbp < 2; nbp++) {
                    LDSM4(bh[nbp], wHiB + b_off[nbp] + kb);
                    LDSM4(bl[nbp], wLoB + b_off[nbp] + kb);
                }
                #pragma unroll
                for (int nb = 0; nb < 4; nb++)
                    #pragma unroll
                    for (int mb = 0; mb < 2; mb++)
                        MMA16816(acc[mb][nb], ah[mb], &bh[nb >> 1][(nb & 1) * 2]);
                #pragma unroll
                for (int nb = 0; nb < 4; nb++)
                    #pragma unroll
                    for (int mb = 0; mb < 2; mb++)
                        MMA16816(acc[mb][nb], ah[mb], &bl[nb >> 1][(nb & 1) * 2]);
                #pragma unroll
                for (int nb = 0; nb < 4; nb++)
                    #pragma unroll
                    for (int mb = 0; mb < 2; mb++)
                        MMA16816(acc[mb][nb], al[mb], &bh[nb >> 1][(nb & 1) * 2]);
            }

            if (c < 3) {
                #pragma unroll
                for (int it = 0; it < 4; it++) {
                    int idx = tid + it * 512;
                    int m = idx >> 4, kq = (idx & 15) * 4;
                    split_store(sA + nxt * A_BUF_ELEMS + m * APITCH + kq,
                                sA + nxt * A_BUF_ELEMS + A_HL_ELEMS + m * APITCH + kq,
                                pf[it]);
                }
                __syncthreads();
            }
        }

        // ---- epilogue ----
        #pragma unroll
        for (int mb = 0; mb < 2; mb++) {
            #pragma unroll
            for (int nb = 0; nb < 4; nb++) {
                int gr = m0 + mwb + mb * 16 + tq;
                int gc = n0 + nwb + nb * 8 + tr * 2;
                float2 bv = *(const float2*)(bias + gc);
                #pragma unroll
                for (int half = 0; half < 2; half++) {
                    int r = gr + half * 8;
                    float p0 = acc[mb][nb][half * 2 + 0] + bv.x;
                    float p1 = acc[mb][nb][half * 2 + 1] + bv.y;
                    size_t off = (size_t)r * HID + gc;
                    *(float2*)(h2h_out + off) = make_float2(p0, p1);
                    float2 iv = *(const float2*)(i2h_t + off);
                    float2 hn = make_float2(tanh_ap(iv.x + p0),
                                            tanh_ap(iv.y + p1));
                    *(float2*)(Hn + off) = hn;
                    if (t == T_STEPS - 1)
                        *(float2*)(hc1f + off) = hn;
                }
            }
        }

        if (t < T_STEPS - 1) CLUSTER_SYNC();
    }
}

// ============================================================================
// i2h_mma: C = X @ W_i2h^T + b.  (unchanged from R12; 2 CTAs/SM)
// ============================================================================
#define IAP 72
#define I2H_SMEM (4 * 128 * IAP * 2)

__global__ __launch_bounds__(256, 2)
void i2h_mma(const float* __restrict__ X,
             const float* __restrict__ bias,
             float* __restrict__ C)
{
    extern __shared__ __nv_bfloat16 ism[];
    __nv_bfloat16* sWhi = ism;
    __nv_bfloat16* sWlo = sWhi + 128 * IAP;
    __nv_bfloat16* sAhi = sWlo + 128 * IAP;
    __nv_bfloat16* sAlo = sAhi + 128 * IAP;

    const int tid = threadIdx.x;
    const int n0 = blockIdx.x * 128;
    const int m0 = blockIdx.y * 128;

    #pragma unroll
    for (int i = tid; i < 1024; i += 256) {
        int n = i >> 3, k8 = (i & 7) * 8;
        *(uint4*)(sWhi + n * IAP + k8) =
            *(const uint4*)(g_Wihi + (size_t)(n0 + n) * IN_F + k8);
        *(uint4*)(sWlo + n * IAP + k8) =
            *(const uint4*)(g_Wilo + (size_t)(n0 + n) * IN_F + k8);
    }
    #pragma unroll
    for (int it = 0; it < 8; it++) {
        int idx = tid + it * 256;
        int m = idx >> 4, kq = (idx & 15) * 4;
        float4 v = *(const float4*)(X + (size_t)(m0 + m) * IN_F + kq);
        split_store(sAhi + m * IAP + kq, sAlo + m * IAP + kq, v);
    }
    __syncthreads();

    const int w = tid >> 5, lane = tid & 31;
    const int mwb = (w >> 1) * 32;
    const int nwb = (w & 1) * 64;
    const int tq = lane >> 2, tr = lane & 3;
    const int quad = lane >> 3, rl = lane & 7;

    uint32_t a_off[2], b_off[4];
    #pragma unroll
    for (int mb = 0; mb < 2; mb++)
        a_off[mb] = (uint32_t)(((mwb + mb * 16 + rl + (quad & 1) * 8) * IAP
                                + (quad >> 1) * 8) * 2);
    #pragma unroll
    for (int nbp = 0; nbp < 4; nbp++)
        b_off[nbp] = (uint32_t)(((nwb + (nbp * 2 + (quad >> 1)) * 8 + rl) * IAP
                                 + (quad & 1) * 8) * 2);

    const uint32_t smb = smem_u32(ism);
    const uint32_t wHiB = smb;
    const uint32_t wLoB = smb + 128 * IAP * 2;
    const uint32_t aHiB = smb + 2 * 128 * IAP * 2;
    const uint32_t aLoB = smb + 3 * 128 * IAP * 2;

    float acc[2][8][4];
    #pragma unroll
    for (int mb = 0; mb < 2; mb++)
        #pragma unroll
        for (int nb = 0; nb < 8; nb++)
            #pragma unroll
            for (int q = 0; q < 4; q++) acc[mb][nb][q] = 0.f;

    #pragma unroll
    for (int kk = 0; kk < 64; kk += 16) {
        uint32_t ah[2][4], al[2][4], bh[4][4], bl[4][4];
        #pragma unroll
        for (int mb = 0; mb < 2; mb++) {
            LDSM4(ah[mb], aHiB + a_off[mb] + kk * 2);
            LDSM4(al[mb], aLoB + a_off[mb] + kk * 2);
        }
        #pragma unroll
        for (int nbp = 0; nbp < 4; nbp++) {
            LDSM4(bh[nbp], wHiB + b_off[nbp] + kk * 2);
            LDSM4(bl[nbp], wLoB + b_off[nbp] + kk * 2);
        }
        #pragma unroll
        for (int nb = 0; nb < 8; nb++)
            #pragma unroll
            for (int mb = 0; mb < 2; mb++)
                MMA16816(acc[mb][nb], ah[mb], &bh[nb >> 1][(nb & 1) * 2]);
        #pragma unroll
        for (int nb = 0; nb < 8; nb++)
            #pragma unroll
            for (int mb = 0; mb < 2; mb++)
                MMA16816(acc[mb][nb], ah[mb], &bl[nb >> 1][(nb & 1) * 2]);
        #pragma unroll
        for (int nb = 0; nb < 8; nb++)
            #pragma unroll
            for (int mb = 0; mb < 2; mb++)
                MMA16816(acc[mb][nb], al[mb], &bh[nb >> 1][(nb & 1) * 2]);
    }

    #pragma unroll
    for (int mb = 0; mb < 2; mb++) {
        #pragma unroll
        for (int nb = 0; nb < 8; nb++) {
            int gr = m0 + mwb + mb * 16 + tq;
            int gc = n0 + nwb + nb * 8 + tr * 2;
            float2 bv = *(const float2*)(bias + gc);
            #pragma unroll
            for (int half = 0; half < 2; half++) {
                size_t off = (size_t)(gr + half * 8) * HID + gc;
                *(float2*)(C + off) =
                    make_float2(acc[mb][nb][half * 2 + 0] + bv.x,
                                acc[mb][nb][half * 2 + 1] + bv.y);
            }
        }
    }
}

// ============================================================================
// head_mma (unchanged from R12)
// ============================================================================
#define HWP 264
#define HAP 72
#define HW_ELEMS (64 * HWP)
#define HA_HL   (128 * HAP)
#define HA_BUF  (2 * HA_HL)
#define HA_BASE (2 * HW_ELEMS)
#define HEAD_SMEM ((HA_BASE + 2 * HA_BUF) * 2)

__global__ __launch_bounds__(256, 1)
void head_mma(const float* __restrict__ i2h, const float* __restrict__ h2h,
              const float* __restrict__ bo,
              const float* __restrict__ Wf, const float* __restrict__ bf,
              float* __restrict__ outseq)
{
    extern __shared__ __nv_bfloat16 hsm[];
    __nv_bfloat16* sWhi = hsm;
    __nv_bfloat16* sWlo = hsm + HW_ELEMS;
    __nv_bfloat16* sA   = hsm + HA_BASE;
    __shared__ float wf[NCLS * OUT_F];
    __shared__ float bfs[NCLS];

    const int tid = threadIdx.x;
    const int m0 = blockIdx.x * 128;

    wf[tid]       = Wf[tid];
    wf[tid + 256] = Wf[tid + 256];
    if (tid < NCLS) bfs[tid] = bf[tid];

    #pragma unroll
    for (int i = tid; i < 2048; i += 256) {
        int n = i >> 5, k8 = (i & 31) * 8;
        *(uint4*)(sWhi + n * HWP + k8) =
            *(const uint4*)(g_Wohi + (size_t)n * HID + k8);
        *(uint4*)(sWlo + n * HWP + k8) =
            *(const uint4*)(g_Wolo + (size_t)n * HID + k8);
    }

    const int w = tid >> 5, lane = tid & 31;
    const int mwb = (w >> 1) * 32;
    const int nwb = (w & 1) * 32;
    const int tq = lane >> 2, tr = lane & 3;
    const int quad = lane >> 3, rl = lane & 7;

    uint32_t a_off[2], b_off[2];
    #pragma unroll
    for (int mb = 0; mb < 2; mb++)
        a_off[mb] = (uint32_t)(((mwb + mb * 16 + rl + (quad & 1) * 8) * HAP
                                + (quad >> 1) * 8) * 2);
    #pragma unroll
    for (int nbp = 0; nbp < 2; nbp++)
        b_off[nbp] = (uint32_t)(((nwb + (nbp * 2 + (quad >> 1)) * 8 + rl) * HWP
                                 + (quad & 1) * 8) * 2);

    const uint32_t smb = smem_u32(hsm);
    const uint32_t wHiB = smb;
    const uint32_t wLoB = smb + HW_ELEMS * 2;
    const uint32_t aB   = smb + HA_BASE * 2;

    float acc[2][4][4];
    #pragma unroll
    for (int mb = 0; mb < 2; mb++)
        #pragma unroll
        for (int nb = 0; nb < 4; nb++)
            #pragma unroll
            for (int q = 0; q < 4; q++) acc[mb][nb][q] = 0.f;

    float4 pfi[8], pfh[8];
    #pragma unroll
    for (int it = 0; it < 8; it++) {
        int idx = tid + it * 256;
        int m = idx >> 4, kq = (idx & 15) * 4;
        size_t off = (size_t)(m0 + m) * HID + kq;
        pfi[it] = *(const float4*)(i2h + off);
        pfh[it] = *(const float4*)(h2h + off);
    }
    #pragma unroll
    for (int it = 0; it < 8; it++) {
        int idx = tid + it * 256;
        int m = idx >> 4, kq = (idx & 15) * 4;
        float4 v;
        v.x = tanh_ap(pfi[it].x + pfh[it].x);
        v.y = tanh_ap(pfi[it].y + pfh[it].y);
        v.z = tanh_ap(pfi[it].z + pfh[it].z);
        v.w = tanh_ap(pfi[it].w + pfh[it].w);
        split_store(sA + m * HAP + kq, sA + HA_HL + m * HAP + kq, v);
    }
    __syncthreads();

    for (int c = 0; c < 4; c++) {
        const int cur = c & 1, nxt = cur ^ 1;

        if (c < 3) {
            #pragma unroll
            for (int it = 0; it < 8; it++) {
                int idx = tid + it * 256;
                int m = idx >> 4, kq = (idx & 15) * 4;
                size_t off = (size_t)(m0 + m) * HID + (c + 1) * 64 + kq;
                pfi[it] = *(const float4*)(i2h + off);
                pfh[it] = *(const float4*)(h2h + off);
            }
        }

        const uint32_t aHi = aB + cur * (HA_BUF * 2);
        const uint32_t aLo = aHi + HA_HL * 2;
        #pragma unroll
        for (int kk = 0; kk < 64; kk += 16) {
            uint32_t ah[2][4], al[2][4], bh[2][4], bl[2][4];
            #pragma unroll
            for (int mb = 0; mb < 2; mb++) {
                LDSM4(ah[mb], aHi + a_off[mb] + kk * 2);
                LDSM4(al[mb], aLo + a_off[mb] + kk * 2);
            }
            const uint32_t kb = (c * 64 + kk) * 2;
            #pragma unroll
            for (int nbp = 0; nbp < 2; nbp++) {
                LDSM4(bh[nbp], wHiB + b_off[nbp] + kb);
                LDSM4(bl[nbp], wLoB + b_off[nbp] + kb);
            }
            #pragma unroll
            for (int nb = 0; nb < 4; nb++)
                #pragma unroll
                for (int mb = 0; mb < 2; mb++)
                    MMA16816(acc[mb][nb], ah[mb], &bh[nb >> 1][(nb & 1) * 2]);
            #pragma unroll
            for (int nb = 0; nb < 4; nb++)
                #pragma unroll
                for (int mb = 0; mb < 2; mb++)
                    MMA16816(acc[mb][nb], ah[mb], &bl[nb >> 1][(nb & 1) * 2]);
            #pragma unroll
            for (int nb = 0; nb < 4; nb++)
                #pragma unroll
                for (int mb = 0; mb < 2; mb++)
                    MMA16816(acc[mb][nb], al[mb], &bh[nb >> 1][(nb & 1) * 2]);
        }

        if (c < 3) {
            #pragma unroll
            for (int it = 0; it < 8; it++) {
                int idx = tid + it * 256;
                int m = idx >> 4, kq = (idx & 15) * 4;
                float4 v;
                v.x = tanh_ap(pfi[it].x + pfh[it].x);
                v.y = tanh_ap(pfi[it].y + pfh[it].y);
                v.z = tanh_ap(pfi[it].z + pfh[it].z);
                v.w = tanh_ap(pfi[it].w + pfh[it].w);
                split_store(sA + nxt * HA_BUF + m * HAP + kq,
                            sA + nxt * HA_BUF + HA_HL + m * HAP + kq, v);
            }
            __syncthreads();
        }
    }

    __syncthreads();
    float* Osm = (float*)sA;
    #pragma unroll
    for (int mb = 0; mb < 2; mb++) {
        #pragma unroll
        for (int nb = 0; nb < 4; nb++) {
            int lr = mwb + mb * 16 + tq;
            int gc = nwb + nb * 8 + tr * 2;
            float2 bv = *(const float2*)(bo + gc);
            #pragma unroll
            for (int half = 0; half < 2; half++) {
                *(float2*)(Osm + (lr + half * 8) * 68 + gc) =
                    make_float2(tanh_ap(acc[mb][nb][half * 2 + 0] + bv.x),
                                tanh_ap(acc[mb][nb][half * 2 + 1] + bv.y));
            }
        }
    }
    __syncthreads();

    #pragma unroll
    for (int i = 0; i < 4; i++) {
        int idx = tid + i * 256;
        int row = idx >> 3;
        int cc  = idx & 7;
        const float* orow = Osm + row * 68;
        const float* wr   = wf + cc * OUT_F;
        float s = bfs[cc];
        #pragma unroll
        for (int o = 0; o < OUT_F; o++) s += orow[o] * wr[o];
        outseq[(size_t)(m0 + row) * NCLS + cc] = s;
    }
}

// ============================================================================
extern "C" void kernel_launch(void* const* d_in, const int* in_sizes, int n_in,
                              void* d_out, int out_size)
{
    const float* x      = (const float*)d_in[0];
    const float* hc1    = (const float*)d_in[2];
    const float* hc2    = (const float*)d_in[3];
    const float* hc3    = (const float*)d_in[4];
    const float* hc4    = (const float*)d_in[5];
    const float* W_i2h  = (const float*)d_in[6];
    const float* b_i2h  = (const float*)d_in[7];
    const float* W_h2h  = (const float*)d_in[8];
    const float* b_h2h  = (const float*)d_in[9];
    const float* W_h2o  = (const float*)d_in[10];
    const float* b_h2o  = (const float*)d_in[11];
    const float* W_fcc  = (const float*)d_in[12];
    const float* b_fcc  = (const float*)d_in[13];

    float* out = (float*)d_out;
    float* i2h_seq = out + OFF_I2H;
    float* h2h_seq = out + OFF_H2H;

    cudaFuncSetAttribute(step_fused, cudaFuncAttributeMaxDynamicSharedMemorySize,
                         STEP_SMEM);
    cudaFuncSetAttribute(i2h_mma, cudaFuncAttributeMaxDynamicSharedMemorySize,
                         I2H_SMEM);
    cudaFuncSetAttribute(head_mma, cudaFuncAttributeMaxDynamicSharedMemorySize,
                         HEAD_SMEM);

    cudaMemcpyAsync(out + OFF_HC2, hc2, (size_t)SZ_HC * sizeof(float),
                    cudaMemcpyDeviceToDevice);
    cudaMemcpyAsync(out + OFF_HC3, hc3, (size_t)SZ_HC * sizeof(float),
                    cudaMemcpyDeviceToDevice);
    cudaMemcpyAsync(out + OFF_HC4, hc4, (size_t)SZ_HC * sizeof(float),
                    cudaMemcpyDeviceToDevice);

    // 0) split weights into bf16 hi/lo
    prep_w<<<256, 256>>>(W_h2h);
    prep_wi<<<64, 256>>>(W_i2h);
    prep_wo<<<64, 256>>>(W_h2o);

    // 1) i2h over all timesteps (tensor cores, 2 CTAs/SM)
    dim3 g1(2, (T_STEPS * BATCH) / 128);
    i2h_mma<<<g1, 256, I2H_SMEM>>>(x, b_i2h, i2h_seq);

    // 2) ALL 16 recurrence steps: persistent, 2-CTA clusters, 512 threads
    step_fused<<<STEP_CTAS, 512, STEP_SMEM>>>(
        hc1, b_h2h, i2h_seq, h2h_seq, out + OFF_HC1);

    // 3) output head (tensor cores + fused fcc)
    head_mma<<<(T_STEPS * BATCH) / 128, 256, HEAD_SMEM>>>(
        i2h_seq, h2h_seq, b_h2o, W_fcc, b_fcc, out + OFF_OUTSEQ);
}